// round 2
// baseline (speedup 1.0000x reference)
#include <cuda_runtime.h>

// ---------------------------------------------------------------------------
// MultiHeadAttention graph block, GB300 fp32 (f32x2 packed FMA) implementation
// B=2, N=256, NODE_DIM=256, EDGE_DIM=64, H=8, D=32
// Inputs: 0 nodes[2,256,256] 1 edges[2,256,256,64] 2 W_qkv[256,768] 3 b_qkv[768]
//         4 W_ss[64,512] 5 b_ss[512] 6 W_nodes[256,256] 7 b_nodes[256]
//         8 W_edges[256,64] 9 b_edges[64]
// Output: new_nodes [2,256,256] (131072 f32) then new_edges_out [2,256,256,64]
// ---------------------------------------------------------------------------

typedef unsigned long long U64;

__device__ __forceinline__ U64 pk2(float lo, float hi) {
    U64 r; asm("mov.b64 %0,{%1,%2};" : "=l"(r) : "f"(lo), "f"(hi)); return r;
}
__device__ __forceinline__ void fma2(U64& d, U64 a, U64 b) {
    asm("fma.rn.f32x2 %0,%1,%2,%0;" : "+l"(d) : "l"(a), "l"(b));
}
__device__ __forceinline__ float2 up2(U64 v) {
    float2 r; asm("mov.b64 {%0,%1},%2;" : "=f"(r.x), "=f"(r.y) : "l"(v)); return r;
}

// Scratch (device globals: no allocation allowed)
__device__ float g_QKV[512 * 768];        // qkv rows: [b*256+n][768], q|k|v at col 0/256/512
__device__ float g_att[2 * 8 * 256 * 256]; // logits -> attention in place, layout [b][h][k][q]
__device__ float g_wt[512 * 256];          // weighted [b*256+q][256]

// ---------------------------------------------------------------------------
// Generic small GEMM with bias: C[M,N] = A[M,K] @ B[K,N] + bias  (M,N mult 64, K mult 16)
// ---------------------------------------------------------------------------
__global__ void __launch_bounds__(256) gemm_bias_kernel(
    const float* __restrict__ A, const float* __restrict__ B,
    const float* __restrict__ bias, float* __restrict__ C,
    int M, int K, int N)
{
    __shared__ float sA[16][65];   // [kk][m]
    __shared__ float sB[16][64];   // [kk][n]
    const int nb = N >> 6;
    const int m0 = (blockIdx.x / nb) << 6;
    const int n0 = (blockIdx.x % nb) << 6;
    const int tm = threadIdx.x >> 4, tn = threadIdx.x & 15;

    float acc[4][4] = {};
    for (int kc = 0; kc < K; kc += 16) {
        {
            const int t = threadIdx.x;
            const int m = t >> 2, k4 = (t & 3) << 2;
            float4 a = *(const float4*)&A[(m0 + m) * K + kc + k4];
            sA[k4 + 0][m] = a.x; sA[k4 + 1][m] = a.y;
            sA[k4 + 2][m] = a.z; sA[k4 + 3][m] = a.w;
            const int kk = t >> 4, n4 = (t & 15) << 2;
            *(float4*)&sB[kk][n4] = *(const float4*)&B[(kc + kk) * N + n0 + n4];
        }
        __syncthreads();
#pragma unroll
        for (int kk = 0; kk < 16; kk++) {
            float a0 = sA[kk][tm * 4 + 0], a1 = sA[kk][tm * 4 + 1];
            float a2 = sA[kk][tm * 4 + 2], a3 = sA[kk][tm * 4 + 3];
            float4 b4 = *(float4*)&sB[kk][tn * 4];
            acc[0][0] += a0 * b4.x; acc[0][1] += a0 * b4.y; acc[0][2] += a0 * b4.z; acc[0][3] += a0 * b4.w;
            acc[1][0] += a1 * b4.x; acc[1][1] += a1 * b4.y; acc[1][2] += a1 * b4.z; acc[1][3] += a1 * b4.w;
            acc[2][0] += a2 * b4.x; acc[2][1] += a2 * b4.y; acc[2][2] += a2 * b4.z; acc[2][3] += a2 * b4.w;
            acc[3][0] += a3 * b4.x; acc[3][1] += a3 * b4.y; acc[3][2] += a3 * b4.z; acc[3][3] += a3 * b4.w;
        }
        __syncthreads();
    }
    float4 bb = *(const float4*)&bias[n0 + tn * 4];
#pragma unroll
    for (int i = 0; i < 4; i++) {
        float4 o = make_float4(acc[i][0] + bb.x, acc[i][1] + bb.y,
                               acc[i][2] + bb.z, acc[i][3] + bb.w);
        *(float4*)&C[(m0 + tm * 4 + i) * N + n0 + tn * 4] = o;
    }
}

// ---------------------------------------------------------------------------
// Main fused edge kernel. Block = (b, q, 32-k tile). 256 threads.
// Phase A: ss GEMM [32 pairs][512] = edges_tile[32,64] @ W_ss[64,512]  (f32x2)
// Phase B: ne = q*k*(1+scale)+shift ; logits ; lrelu(ne) -> smem
// Phase C: out = lrelu(ne)[32,256] @ W_edges[256,64] + b_edges       (f32x2)
// ---------------------------------------------------------------------------
__global__ void __launch_bounds__(256, 2) main_edge_kernel(
    const float* __restrict__ edges, const float* __restrict__ W_ss,
    const float* __restrict__ b_ss, const float* __restrict__ W_edges,
    const float* __restrict__ b_edges, float* __restrict__ out_edges,
    float* __restrict__ logits)
{
    extern __shared__ float sm[];
    float* sA   = sm;                 // edges^T [64 kk][33 pairs]      (2112 f)
    float* sQ   = sm + 2112;          // q row (256 f)
    float* sBNE = sm + 2112 + 256;    // W_ss stage [16][512] then NE [32][264] (8448 f)

    const int bid = blockIdx.x;
    const int b  = bid >> 11;
    const int q  = (bid >> 3) & 255;
    const int k0 = (bid & 7) << 5;
    const int tid = threadIdx.x;
    const int tc = tid & 31, tp = tid >> 5;
    const int cb = tc << 3;            // c base (8 contiguous c per thread)

    // load edges tile transposed + q row
    {
        const float* ep = edges + (((size_t)(b << 8) + q) * 256 + k0) * 64;
#pragma unroll
        for (int r = 0; r < 2; r++) {
            int idx4 = tid + r * 256;           // 0..511 float4s
            float4 v = *(const float4*)(ep + idx4 * 4);
            int pair = idx4 >> 4;
            int kk = (idx4 & 15) << 2;
            sA[(kk + 0) * 33 + pair] = v.x; sA[(kk + 1) * 33 + pair] = v.y;
            sA[(kk + 2) * 33 + pair] = v.z; sA[(kk + 3) * 33 + pair] = v.w;
        }
        if (tid < 64)
            *(float4*)&sQ[tid * 4] = *(const float4*)&g_QKV[((b << 8) + q) * 768 + tid * 4];
    }

    // -------- Phase A: ss GEMM, packed accumulators --------
    U64 aS[4][4] = {}, aC[4][4] = {};   // [pair][cpack] shift / scale
    for (int s = 0; s < 4; s++) {
        __syncthreads();
#pragma unroll
        for (int r = 0; r < 8; r++) {
            int idx4 = tid + r * 256;                 // 2048 float4s = 16x512
            int row = idx4 >> 7, col = (idx4 & 127) << 2;
            *(float4*)&sBNE[row * 512 + col] =
                *(const float4*)&W_ss[(s * 16 + row) * 512 + col];
        }
        __syncthreads();
#pragma unroll
        for (int kk = 0; kk < 16; kk++) {
            const float* ar = &sA[(s * 16 + kk) * 33 + (tp << 2)];
            float a0 = ar[0], a1 = ar[1], a2 = ar[2], a3 = ar[3];
            const float* br = &sBNE[kk * 512];
            float4 s0 = *(const float4*)(br + cb),       s1 = *(const float4*)(br + cb + 4);
            float4 c0 = *(const float4*)(br + 256 + cb), c1 = *(const float4*)(br + 256 + cb + 4);
            U64 bS[4] = { pk2(s0.x, s0.y), pk2(s0.z, s0.w), pk2(s1.x, s1.y), pk2(s1.z, s1.w) };
            U64 bC[4] = { pk2(c0.x, c0.y), pk2(c0.z, c0.w), pk2(c1.x, c1.y), pk2(c1.z, c1.w) };
            U64 A0 = pk2(a0, a0), A1 = pk2(a1, a1), A2 = pk2(a2, a2), A3 = pk2(a3, a3);
#pragma unroll
            for (int j = 0; j < 4; j++) {
                fma2(aS[0][j], A0, bS[j]); fma2(aC[0][j], A0, bC[j]);
                fma2(aS[1][j], A1, bS[j]); fma2(aC[1][j], A1, bC[j]);
                fma2(aS[2][j], A2, bS[j]); fma2(aC[2][j], A2, bC[j]);
                fma2(aS[3][j], A3, bS[j]); fma2(aC[3][j], A3, bC[j]);
            }
        }
    }
    __syncthreads();   // all reads of W_ss stage done before NE overwrites it

    // -------- Phase B: ne, logits, lrelu -> smem --------
    float bsh[8], bsc[8], qv[8];
    *(float4*)&bsh[0] = *(const float4*)&b_ss[cb];
    *(float4*)&bsh[4] = *(const float4*)&b_ss[cb + 4];
    *(float4*)&bsc[0] = *(const float4*)&b_ss[256 + cb];
    *(float4*)&bsc[4] = *(const float4*)&b_ss[256 + cb + 4];
    *(float4*)&qv[0] = *(float4*)&sQ[cb];
    *(float4*)&qv[4] = *(float4*)&sQ[cb + 4];

#pragma unroll
    for (int p = 0; p < 4; p++) {
        const int pi = (tp << 2) + p;
        const int k = k0 + pi;
        const float* kr = &g_QKV[((b << 8) + k) * 768 + 256 + cb];
        float kv[8];
        *(float4*)&kv[0] = *(const float4*)kr;
        *(float4*)&kv[4] = *(const float4*)(kr + 4);
        float lg = 0.f;
        float ne[8];
#pragma unroll
        for (int jj = 0; jj < 4; jj++) {
            float2 sh2 = up2(aS[p][jj]);
            float2 sc2 = up2(aC[p][jj]);
            float sh0 = sh2.x + bsh[2 * jj],     sh1 = sh2.y + bsh[2 * jj + 1];
            float sc0 = sc2.x + bsc[2 * jj],     sc1 = sc2.y + bsc[2 * jj + 1];
            float qk0 = qv[2 * jj] * kv[2 * jj];
            float qk1 = qv[2 * jj + 1] * kv[2 * jj + 1];
            float n0 = fmaf(qk0, sc0, qk0) + sh0;
            float n1 = fmaf(qk1, sc1, qk1) + sh1;
            lg += n0 + n1;
            ne[2 * jj]     = n0 > 0.f ? n0 : 0.1f * n0;
            ne[2 * jj + 1] = n1 > 0.f ? n1 : 0.1f * n1;
        }
        float* nr = &sBNE[pi * 264 + cb];
        *(float4*)nr       = make_float4(ne[0], ne[1], ne[2], ne[3]);
        *(float4*)(nr + 4) = make_float4(ne[4], ne[5], ne[6], ne[7]);
        lg += __shfl_xor_sync(0xffffffffu, lg, 1);
        lg += __shfl_xor_sync(0xffffffffu, lg, 2);
        if ((tc & 3) == 0) {
            int h = tc >> 2;
            logits[(((b << 3) + h) * 256 + k) * 256 + q] = lg * 0.17677669529663687f;
        }
    }
    __syncthreads();   // NE fully written

    // -------- Phase C: edge output GEMM --------
    const int tp2 = tid >> 4, te = tid & 15;   // pairs 2*tp2, e = te*4
    U64 o[2][2] = {};
    float* sW = sA;   // reuse edges-tile region (2048 <= 2112 floats)
    for (int s2 = 0; s2 < 8; s2++) {
#pragma unroll
        for (int r = 0; r < 2; r++) {
            int idx4 = tid + r * 256;            // 512 float4s = 32x64
            int row = idx4 >> 4, col = (idx4 & 15) << 2;
            *(float4*)&sW[row * 64 + col] =
                *(const float4*)&W_edges[(s2 * 32 + row) * 64 + col];
        }
        __syncthreads();
#pragma unroll
        for (int kk = 0; kk < 32; kk++) {
            int k2 = s2 * 32 + kk;
            float n0 = sBNE[(tp2 * 2) * 264 + k2];
            float n1 = sBNE[(tp2 * 2 + 1) * 264 + k2];
            float4 w = *(const float4*)&sW[kk * 64 + te * 4];
            U64 w01 = pk2(w.x, w.y), w23 = pk2(w.z, w.w);
            U64 N0 = pk2(n0, n0), N1 = pk2(n1, n1);
            fma2(o[0][0], N0, w01); fma2(o[0][1], N0, w23);
            fma2(o[1][0], N1, w01); fma2(o[1][1], N1, w23);
        }
        __syncthreads();
    }
    float4 be = *(const float4*)&b_edges[te * 4];
#pragma unroll
    for (int p = 0; p < 2; p++) {
        float2 x0 = up2(o[p][0]), x1 = up2(o[p][1]);
        float4 res = make_float4(x0.x + be.x, x0.y + be.y, x1.x + be.z, x1.y + be.w);
        int k = k0 + tp2 * 2 + p;
        *(float4*)&out_edges[(((size_t)(b << 8) + q) * 256 + k) * 64 + te * 4] = res;
    }
}

// ---------------------------------------------------------------------------
// Softmax over q for each (b,h,k). Rows of g_att are contiguous in q. In place.
// ---------------------------------------------------------------------------
__global__ void __launch_bounds__(256) softmax_q_kernel(float* __restrict__ lg)
{
    const int row = blockIdx.x * 8 + (threadIdx.x >> 5);
    const int lane = threadIdx.x & 31;
    float* p = lg + (size_t)row * 256;
    float4 v0 = *(float4*)&p[lane * 8];
    float4 v1 = *(float4*)&p[lane * 8 + 4];
    float v[8] = { v0.x, v0.y, v0.z, v0.w, v1.x, v1.y, v1.z, v1.w };
    float m = v[0];
#pragma unroll
    for (int i = 1; i < 8; i++) m = fmaxf(m, v[i]);
#pragma unroll
    for (int off = 16; off > 0; off >>= 1) m = fmaxf(m, __shfl_xor_sync(0xffffffffu, m, off));
    float s = 0.f;
#pragma unroll
    for (int i = 0; i < 8; i++) { v[i] = __expf(v[i] - m); s += v[i]; }
#pragma unroll
    for (int off = 16; off > 0; off >>= 1) s += __shfl_xor_sync(0xffffffffu, s, off);
    float inv = 1.f / s;
    *(float4*)&p[lane * 8]     = make_float4(v[0] * inv, v[1] * inv, v[2] * inv, v[3] * inv);
    *(float4*)&p[lane * 8 + 4] = make_float4(v[4] * inv, v[5] * inv, v[6] * inv, v[7] * inv);
}

// ---------------------------------------------------------------------------
// weighted[b,q,h*32+d] = sum_k att[b,h,k,q] * V[b,k,h*32+d]
// grid (qc=4, h=8, b=2), 256 threads = 64 q x (4 groups of 8 d)
// ---------------------------------------------------------------------------
__global__ void __launch_bounds__(256) attnv_kernel(const float* __restrict__ att,
                                                    float* __restrict__ wt)
{
    __shared__ float sv[32][32];
    const int b = blockIdx.z, h = blockIdx.y, qc = blockIdx.x;
    const int dg = threadIdx.x >> 6, qq = threadIdx.x & 63;
    const int q = qc * 64 + qq;
    float acc[8] = {};
    for (int kc = 0; kc < 8; kc++) {
        __syncthreads();
        {
            int row = threadIdx.x >> 3, c4 = (threadIdx.x & 7) << 2;
            *(float4*)&sv[row][c4] =
                *(const float4*)&g_QKV[((b << 8) + kc * 32 + row) * 768 + 512 + h * 32 + c4];
        }
        __syncthreads();
        const float* ap = att + (((size_t)((b << 3) + h)) * 256 + kc * 32) * 256 + q;
#pragma unroll
        for (int kk = 0; kk < 32; kk++) {
            float a = ap[(size_t)kk * 256];
            float4 u0 = *(float4*)&sv[kk][dg * 8];
            float4 u1 = *(float4*)&sv[kk][dg * 8 + 4];
            acc[0] += a * u0.x; acc[1] += a * u0.y; acc[2] += a * u0.z; acc[3] += a * u0.w;
            acc[4] += a * u1.x; acc[5] += a * u1.y; acc[6] += a * u1.z; acc[7] += a * u1.w;
        }
    }
    float* wp = &wt[((b << 8) + q) * 256 + h * 32 + dg * 8];
    *(float4*)wp       = make_float4(acc[0], acc[1], acc[2], acc[3]);
    *(float4*)(wp + 4) = make_float4(acc[4], acc[5], acc[6], acc[7]);
}

// ---------------------------------------------------------------------------
extern "C" void kernel_launch(void* const* d_in, const int* in_sizes, int n_in,
                              void* d_out, int out_size)
{
    const float* nodes   = (const float*)d_in[0];
    const float* edges   = (const float*)d_in[1];
    const float* W_qkv   = (const float*)d_in[2];
    const float* b_qkv   = (const float*)d_in[3];
    const float* W_ss    = (const float*)d_in[4];
    const float* b_ss    = (const float*)d_in[5];
    const float* W_nodes = (const float*)d_in[6];
    const float* b_nodes = (const float*)d_in[7];
    const float* W_edges = (const float*)d_in[8];
    const float* b_edges = (const float*)d_in[9];

    float* out_nodes = (float*)d_out;
    float* out_edges = out_nodes + 512 * 256;

    float *qkvp = nullptr, *attp = nullptr, *wtp = nullptr;
    cudaGetSymbolAddress((void**)&qkvp, g_QKV);
    cudaGetSymbolAddress((void**)&attp, g_att);
    cudaGetSymbolAddress((void**)&wtp, g_wt);

    // 1) qkv = nodes @ W_qkv + b_qkv : [512,768], K=256
    gemm_bias_kernel<<<(512 / 64) * (768 / 64), 256>>>(nodes, W_qkv, b_qkv, qkvp, 512, 256, 768);

    // 2) fused edge pipeline (ss GEMM + ne + logits + lrelu + edge-out GEMM)
    const int smem = (2112 + 256 + 8448) * sizeof(float);  // 43264 B
    main_edge_kernel<<<2 * 256 * 8, 256, smem>>>(edges, W_ss, b_ss, W_edges, b_edges,
                                                 out_edges, attp);

    // 3) softmax over q for each (b,h,k) — 4096 rows, 8 rows/block
    softmax_q_kernel<<<512, 256>>>(attp);

    // 4) weighted = einsum('bhqk,bhkd->bqhd', att, v)
    attnv_kernel<<<dim3(4, 8, 2), 256>>>(attp, wtp);

    // 5) new_nodes = weighted @ W_nodes + b_nodes : [512,256], K=256
    gemm_bias_kernel<<<(512 / 64) * (256 / 64), 256>>>(wtp, W_nodes, b_nodes, out_nodes,
                                                       512, 256, 256);
}

// round 3
// speedup vs baseline: 1.0004x; 1.0004x over previous
#include <cuda_runtime.h>

// ---------------------------------------------------------------------------
// MultiHeadAttention graph block, GB300 fp32 (f32x2 packed FMA) implementation
// B=2, N=256, NODE_DIM=256, EDGE_DIM=64, H=8, D=32
// Inputs: 0 nodes[2,256,256] 1 edges[2,256,256,64] 2 W_qkv[256,768] 3 b_qkv[768]
//         4 W_ss[64,512] 5 b_ss[512] 6 W_nodes[256,256] 7 b_nodes[256]
//         8 W_edges[256,64] 9 b_edges[64]
// Output: new_nodes [2,256,256] (131072 f32) then new_edges_out [2,256,256,64]
// ---------------------------------------------------------------------------

typedef unsigned long long U64;

__device__ __forceinline__ U64 pk2(float lo, float hi) {
    U64 r; asm("mov.b64 %0,{%1,%2};" : "=l"(r) : "f"(lo), "f"(hi)); return r;
}
__device__ __forceinline__ void fma2(U64& d, U64 a, U64 b) {
    asm("fma.rn.f32x2 %0,%1,%2,%0;" : "+l"(d) : "l"(a), "l"(b));
}
__device__ __forceinline__ float2 up2(U64 v) {
    float2 r; asm("mov.b64 {%0,%1},%2;" : "=f"(r.x), "=f"(r.y) : "l"(v)); return r;
}

// Scratch (device globals: no allocation allowed)
__device__ float g_QKV[512 * 768];        // qkv rows: [b*256+n][768], q|k|v at col 0/256/512
__device__ float g_att[2 * 8 * 256 * 256]; // logits -> attention in place, layout [b][h][k][q]
__device__ float g_wt[512 * 256];          // weighted [b*256+q][256]

// ---------------------------------------------------------------------------
// Generic small GEMM with bias: C[M,N] = A[M,K] @ B[K,N] + bias  (M,N mult 64, K mult 16)
// ---------------------------------------------------------------------------
__global__ void __launch_bounds__(256) gemm_bias_kernel(
    const float* __restrict__ A, const float* __restrict__ B,
    const float* __restrict__ bias, float* __restrict__ C,
    int M, int K, int N)
{
    __shared__ float sA[16][65];   // [kk][m]
    __shared__ float sB[16][64];   // [kk][n]
    const int nb = N >> 6;
    const int m0 = (blockIdx.x / nb) << 6;
    const int n0 = (blockIdx.x % nb) << 6;
    const int tm = threadIdx.x >> 4, tn = threadIdx.x & 15;

    float acc[4][4] = {};
    for (int kc = 0; kc < K; kc += 16) {
        {
            const int t = threadIdx.x;
            const int m = t >> 2, k4 = (t & 3) << 2;
            float4 a = *(const float4*)&A[(m0 + m) * K + kc + k4];
            sA[k4 + 0][m] = a.x; sA[k4 + 1][m] = a.y;
            sA[k4 + 2][m] = a.z; sA[k4 + 3][m] = a.w;
            const int kk = t >> 4, n4 = (t & 15) << 2;
            *(float4*)&sB[kk][n4] = *(const float4*)&B[(kc + kk) * N + n0 + n4];
        }
        __syncthreads();
#pragma unroll
        for (int kk = 0; kk < 16; kk++) {
            float a0 = sA[kk][tm * 4 + 0], a1 = sA[kk][tm * 4 + 1];
            float a2 = sA[kk][tm * 4 + 2], a3 = sA[kk][tm * 4 + 3];
            float4 b4 = *(float4*)&sB[kk][tn * 4];
            acc[0][0] += a0 * b4.x; acc[0][1] += a0 * b4.y; acc[0][2] += a0 * b4.z; acc[0][3] += a0 * b4.w;
            acc[1][0] += a1 * b4.x; acc[1][1] += a1 * b4.y; acc[1][2] += a1 * b4.z; acc[1][3] += a1 * b4.w;
            acc[2][0] += a2 * b4.x; acc[2][1] += a2 * b4.y; acc[2][2] += a2 * b4.z; acc[2][3] += a2 * b4.w;
            acc[3][0] += a3 * b4.x; acc[3][1] += a3 * b4.y; acc[3][2] += a3 * b4.z; acc[3][3] += a3 * b4.w;
        }
        __syncthreads();
    }
    float4 bb = *(const float4*)&bias[n0 + tn * 4];
#pragma unroll
    for (int i = 0; i < 4; i++) {
        float4 o = make_float4(acc[i][0] + bb.x, acc[i][1] + bb.y,
                               acc[i][2] + bb.z, acc[i][3] + bb.w);
        *(float4*)&C[(m0 + tm * 4 + i) * N + n0 + tn * 4] = o;
    }
}

// ---------------------------------------------------------------------------
// Main fused edge kernel. Block = (b, q, 32-k tile). 256 threads.
// Phase A: ss GEMM [32 pairs][512] = edges_tile[32,64] @ W_ss[64,512]  (f32x2)
// Phase B: ne = q*k*(1+scale)+shift ; logits ; lrelu(ne) -> smem
// Phase C: out = lrelu(ne)[32,256] @ W_edges[256,64] + b_edges       (f32x2)
// ---------------------------------------------------------------------------
__global__ void __launch_bounds__(256, 2) main_edge_kernel(
    const float* __restrict__ edges, const float* __restrict__ W_ss,
    const float* __restrict__ b_ss, const float* __restrict__ W_edges,
    const float* __restrict__ b_edges, float* __restrict__ out_edges,
    float* __restrict__ logits)
{
    extern __shared__ float sm[];
    float* sA   = sm;                 // edges^T [64 kk][33 pairs]      (2112 f)
    float* sQ   = sm + 2112;          // q row (256 f)
    float* sBNE = sm + 2112 + 256;    // W_ss stage [16][512] then NE [32][264] (8448 f)

    const int bid = blockIdx.x;
    const int b  = bid >> 11;
    const int q  = (bid >> 3) & 255;
    const int k0 = (bid & 7) << 5;
    const int tid = threadIdx.x;
    const int tc = tid & 31, tp = tid >> 5;
    const int cb = tc << 3;            // c base (8 contiguous c per thread)

    // load edges tile transposed + q row
    {
        const float* ep = edges + (((size_t)(b << 8) + q) * 256 + k0) * 64;
#pragma unroll
        for (int r = 0; r < 2; r++) {
            int idx4 = tid + r * 256;           // 0..511 float4s
            float4 v = *(const float4*)(ep + idx4 * 4);
            int pair = idx4 >> 4;
            int kk = (idx4 & 15) << 2;
            sA[(kk + 0) * 33 + pair] = v.x; sA[(kk + 1) * 33 + pair] = v.y;
            sA[(kk + 2) * 33 + pair] = v.z; sA[(kk + 3) * 33 + pair] = v.w;
        }
        if (tid < 64)
            *(float4*)&sQ[tid * 4] = *(const float4*)&g_QKV[((b << 8) + q) * 768 + tid * 4];
    }

    // -------- Phase A: ss GEMM, packed accumulators --------
    U64 aS[4][4] = {}, aC[4][4] = {};   // [pair][cpack] shift / scale
    for (int s = 0; s < 4; s++) {
        __syncthreads();
#pragma unroll
        for (int r = 0; r < 8; r++) {
            int idx4 = tid + r * 256;                 // 2048 float4s = 16x512
            int row = idx4 >> 7, col = (idx4 & 127) << 2;
            *(float4*)&sBNE[row * 512 + col] =
                *(const float4*)&W_ss[(s * 16 + row) * 512 + col];
        }
        __syncthreads();
#pragma unroll
        for (int kk = 0; kk < 16; kk++) {
            const float* ar = &sA[(s * 16 + kk) * 33 + (tp << 2)];
            float a0 = ar[0], a1 = ar[1], a2 = ar[2], a3 = ar[3];
            const float* br = &sBNE[kk * 512];
            float4 s0 = *(const float4*)(br + cb),       s1 = *(const float4*)(br + cb + 4);
            float4 c0 = *(const float4*)(br + 256 + cb), c1 = *(const float4*)(br + 256 + cb + 4);
            U64 bS[4] = { pk2(s0.x, s0.y), pk2(s0.z, s0.w), pk2(s1.x, s1.y), pk2(s1.z, s1.w) };
            U64 bC[4] = { pk2(c0.x, c0.y), pk2(c0.z, c0.w), pk2(c1.x, c1.y), pk2(c1.z, c1.w) };
            U64 A0 = pk2(a0, a0), A1 = pk2(a1, a1), A2 = pk2(a2, a2), A3 = pk2(a3, a3);
#pragma unroll
            for (int j = 0; j < 4; j++) {
                fma2(aS[0][j], A0, bS[j]); fma2(aC[0][j], A0, bC[j]);
                fma2(aS[1][j], A1, bS[j]); fma2(aC[1][j], A1, bC[j]);
                fma2(aS[2][j], A2, bS[j]); fma2(aC[2][j], A2, bC[j]);
                fma2(aS[3][j], A3, bS[j]); fma2(aC[3][j], A3, bC[j]);
            }
        }
    }
    __syncthreads();   // all reads of W_ss stage done before NE overwrites it

    // -------- Phase B: ne, logits, lrelu -> smem --------
    float bsh[8], bsc[8], qv[8];
    *(float4*)&bsh[0] = *(const float4*)&b_ss[cb];
    *(float4*)&bsh[4] = *(const float4*)&b_ss[cb + 4];
    *(float4*)&bsc[0] = *(const float4*)&b_ss[256 + cb];
    *(float4*)&bsc[4] = *(const float4*)&b_ss[256 + cb + 4];
    *(float4*)&qv[0] = *(float4*)&sQ[cb];
    *(float4*)&qv[4] = *(float4*)&sQ[cb + 4];

#pragma unroll
    for (int p = 0; p < 4; p++) {
        const int pi = (tp << 2) + p;
        const int k = k0 + pi;
        const float* kr = &g_QKV[((b << 8) + k) * 768 + 256 + cb];
        float kv[8];
        *(float4*)&kv[0] = *(const float4*)kr;
        *(float4*)&kv[4] = *(const float4*)(kr + 4);
        float lg = 0.f;
        float ne[8];
#pragma unroll
        for (int jj = 0; jj < 4; jj++) {
            float2 sh2 = up2(aS[p][jj]);
            float2 sc2 = up2(aC[p][jj]);
            float sh0 = sh2.x + bsh[2 * jj],     sh1 = sh2.y + bsh[2 * jj + 1];
            float sc0 = sc2.x + bsc[2 * jj],     sc1 = sc2.y + bsc[2 * jj + 1];
            float qk0 = qv[2 * jj] * kv[2 * jj];
            float qk1 = qv[2 * jj + 1] * kv[2 * jj + 1];
            float n0 = fmaf(qk0, sc0, qk0) + sh0;
            float n1 = fmaf(qk1, sc1, qk1) + sh1;
            lg += n0 + n1;
            ne[2 * jj]     = n0 > 0.f ? n0 : 0.1f * n0;
            ne[2 * jj + 1] = n1 > 0.f ? n1 : 0.1f * n1;
        }
        float* nr = &sBNE[pi * 264 + cb];
        *(float4*)nr       = make_float4(ne[0], ne[1], ne[2], ne[3]);
        *(float4*)(nr + 4) = make_float4(ne[4], ne[5], ne[6], ne[7]);
        lg += __shfl_xor_sync(0xffffffffu, lg, 1);
        lg += __shfl_xor_sync(0xffffffffu, lg, 2);
        if ((tc & 3) == 0) {
            int h = tc >> 2;
            logits[(((b << 3) + h) * 256 + k) * 256 + q] = lg * 0.17677669529663687f;
        }
    }
    __syncthreads();   // NE fully written

    // -------- Phase C: edge output GEMM --------
    const int tp2 = tid >> 4, te = tid & 15;   // pairs 2*tp2, e = te*4
    U64 o[2][2] = {};
    float* sW = sA;   // reuse edges-tile region (2048 <= 2112 floats)
    for (int s2 = 0; s2 < 8; s2++) {
#pragma unroll
        for (int r = 0; r < 2; r++) {
            int idx4 = tid + r * 256;            // 512 float4s = 32x64
            int row = idx4 >> 4, col = (idx4 & 15) << 2;
            *(float4*)&sW[row * 64 + col] =
                *(const float4*)&W_edges[(s2 * 32 + row) * 64 + col];
        }
        __syncthreads();
#pragma unroll
        for (int kk = 0; kk < 32; kk++) {
            int k2 = s2 * 32 + kk;
            float n0 = sBNE[(tp2 * 2) * 264 + k2];
            float n1 = sBNE[(tp2 * 2 + 1) * 264 + k2];
            float4 w = *(const float4*)&sW[kk * 64 + te * 4];
            U64 w01 = pk2(w.x, w.y), w23 = pk2(w.z, w.w);
            U64 N0 = pk2(n0, n0), N1 = pk2(n1, n1);
            fma2(o[0][0], N0, w01); fma2(o[0][1], N0, w23);
            fma2(o[1][0], N1, w01); fma2(o[1][1], N1, w23);
        }
        __syncthreads();
    }
    float4 be = *(const float4*)&b_edges[te * 4];
#pragma unroll
    for (int p = 0; p < 2; p++) {
        float2 x0 = up2(o[p][0]), x1 = up2(o[p][1]);
        float4 res = make_float4(x0.x + be.x, x0.y + be.y, x1.x + be.z, x1.y + be.w);
        int k = k0 + tp2 * 2 + p;
        *(float4*)&out_edges[(((size_t)(b << 8) + q) * 256 + k) * 64 + te * 4] = res;
    }
}

// ---------------------------------------------------------------------------
// Softmax over q for each (b,h,k). Rows of g_att are contiguous in q. In place.
// ---------------------------------------------------------------------------
__global__ void __launch_bounds__(256) softmax_q_kernel(float* __restrict__ lg)
{
    const int row = blockIdx.x * 8 + (threadIdx.x >> 5);
    const int lane = threadIdx.x & 31;
    float* p = lg + (size_t)row * 256;
    float4 v0 = *(float4*)&p[lane * 8];
    float4 v1 = *(float4*)&p[lane * 8 + 4];
    float v[8] = { v0.x, v0.y, v0.z, v0.w, v1.x, v1.y, v1.z, v1.w };
    float m = v[0];
#pragma unroll
    for (int i = 1; i < 8; i++) m = fmaxf(m, v[i]);
#pragma unroll
    for (int off = 16; off > 0; off >>= 1) m = fmaxf(m, __shfl_xor_sync(0xffffffffu, m, off));
    float s = 0.f;
#pragma unroll
    for (int i = 0; i < 8; i++) { v[i] = __expf(v[i] - m); s += v[i]; }
#pragma unroll
    for (int off = 16; off > 0; off >>= 1) s += __shfl_xor_sync(0xffffffffu, s, off);
    float inv = 1.f / s;
    *(float4*)&p[lane * 8]     = make_float4(v[0] * inv, v[1] * inv, v[2] * inv, v[3] * inv);
    *(float4*)&p[lane * 8 + 4] = make_float4(v[4] * inv, v[5] * inv, v[6] * inv, v[7] * inv);
}

// ---------------------------------------------------------------------------
// weighted[b,q,h*32+d] = sum_k att[b,h,k,q] * V[b,k,h*32+d]
// grid (qc=4, h=8, b=2), 256 threads = 64 q x (4 groups of 8 d)
// ---------------------------------------------------------------------------
__global__ void __launch_bounds__(256) attnv_kernel(const float* __restrict__ att,
                                                    float* __restrict__ wt)
{
    __shared__ float sv[32][32];
    const int b = blockIdx.z, h = blockIdx.y, qc = blockIdx.x;
    const int dg = threadIdx.x >> 6, qq = threadIdx.x & 63;
    const int q = qc * 64 + qq;
    float acc[8] = {};
    for (int kc = 0; kc < 8; kc++) {
        __syncthreads();
        {
            int row = threadIdx.x >> 3, c4 = (threadIdx.x & 7) << 2;
            *(float4*)&sv[row][c4] =
                *(const float4*)&g_QKV[((b << 8) + kc * 32 + row) * 768 + 512 + h * 32 + c4];
        }
        __syncthreads();
        const float* ap = att + (((size_t)((b << 3) + h)) * 256 + kc * 32) * 256 + q;
#pragma unroll
        for (int kk = 0; kk < 32; kk++) {
            float a = ap[(size_t)kk * 256];
            float4 u0 = *(float4*)&sv[kk][dg * 8];
            float4 u1 = *(float4*)&sv[kk][dg * 8 + 4];
            acc[0] += a * u0.x; acc[1] += a * u0.y; acc[2] += a * u0.z; acc[3] += a * u0.w;
            acc[4] += a * u1.x; acc[5] += a * u1.y; acc[6] += a * u1.z; acc[7] += a * u1.w;
        }
    }
    float* wp = &wt[((b << 8) + q) * 256 + h * 32 + dg * 8];
    *(float4*)wp       = make_float4(acc[0], acc[1], acc[2], acc[3]);
    *(float4*)(wp + 4) = make_float4(acc[4], acc[5], acc[6], acc[7]);
}

// ---------------------------------------------------------------------------
extern "C" void kernel_launch(void* const* d_in, const int* in_sizes, int n_in,
                              void* d_out, int out_size)
{
    const float* nodes   = (const float*)d_in[0];
    const float* edges   = (const float*)d_in[1];
    const float* W_qkv   = (const float*)d_in[2];
    const float* b_qkv   = (const float*)d_in[3];
    const float* W_ss    = (const float*)d_in[4];
    const float* b_ss    = (const float*)d_in[5];
    const float* W_nodes = (const float*)d_in[6];
    const float* b_nodes = (const float*)d_in[7];
    const float* W_edges = (const float*)d_in[8];
    const float* b_edges = (const float*)d_in[9];

    float* out_nodes = (float*)d_out;
    float* out_edges = out_nodes + 512 * 256;

    float *qkvp = nullptr, *attp = nullptr, *wtp = nullptr;
    cudaGetSymbolAddress((void**)&qkvp, g_QKV);
    cudaGetSymbolAddress((void**)&attp, g_att);
    cudaGetSymbolAddress((void**)&wtp, g_wt);

    // 1) qkv = nodes @ W_qkv + b_qkv : [512,768], K=256
    gemm_bias_kernel<<<(512 / 64) * (768 / 64), 256>>>(nodes, W_qkv, b_qkv, qkvp, 512, 256, 768);

    // 2) fused edge pipeline (ss GEMM + ne + logits + lrelu + edge-out GEMM)
    const int smem = (2112 + 256 + 8448) * sizeof(float);  // 43264 B
    main_edge_kernel<<<2 * 256 * 8, 256, smem>>>(edges, W_ss, b_ss, W_edges, b_edges,
                                                 out_edges, attp);

    // 3) softmax over q for each (b,h,k) — 4096 rows, 8 rows/block
    softmax_q_kernel<<<512, 256>>>(attp);

    // 4) weighted = einsum('bhqk,bhkd->bqhd', att, v)
    attnv_kernel<<<dim3(4, 8, 2), 256>>>(attp, wtp);

    // 5) new_nodes = weighted @ W_nodes + b_nodes : [512,256], K=256
    gemm_bias_kernel<<<(512 / 64) * (256 / 64), 256>>>(wtp, W_nodes, b_nodes, out_nodes,
                                                       512, 256, 256);
}

// round 7
// speedup vs baseline: 2.4168x; 2.4159x over previous
#include <cuda_runtime.h>
#include <cuda_bf16.h>
#include <cstdint>

// ---------------------------------------------------------------------------
// mma.sync bf16 3-pass implementation (tcgen05 unavailable: harness PTX target
// is plain sm_103). B=2,N=256,NODE=256,EDGE=64,H=8,D=32.
// ---------------------------------------------------------------------------

__device__ __forceinline__ void mma16816(float c[4], const uint32_t a[4],
                                         uint32_t b0, uint32_t b1) {
    asm volatile("mma.sync.aligned.m16n8k16.row.col.f32.bf16.bf16.f32 "
        "{%0,%1,%2,%3},{%4,%5,%6,%7},{%8,%9},{%0,%1,%2,%3};"
        : "+f"(c[0]), "+f"(c[1]), "+f"(c[2]), "+f"(c[3])
        : "r"(a[0]), "r"(a[1]), "r"(a[2]), "r"(a[3]), "r"(b0), "r"(b1));
}
// pack (v0,v1) as bf16 hi image + residual lo image
__device__ __forceinline__ void split2(float v0, float v1, uint32_t& h, uint32_t& l) {
    __nv_bfloat162 hh = __floats2bfloat162_rn(v0, v1);
    float h0 = __bfloat162float(hh.x), h1 = __bfloat162float(hh.y);
    __nv_bfloat162 ll = __floats2bfloat162_rn(v0 - h0, v1 - h1);
    h = *(uint32_t*)&hh; l = *(uint32_t*)&ll;
}

// ===== scratch =====
__device__ float g_QKV[512 * 768];          // [b*256+n][768] q|k|v
__device__ float g_att[2 * 8 * 256 * 256];  // [b][h][k][q]
__device__ float g_wt[512 * 256];
__device__ uint4 g_Wss[8192];   // [pass2][ks4][tp32][lane32] frag-linear bf16x2
__device__ uint4 g_Wed[4096];   // [pass2][ks16][tp4][lane32]  (FIXED: was 2048)

// ===== zero g_wt (pure kernel node; avoids memset in graph) =====
__global__ void __launch_bounds__(256) zero_wt_kernel()
{
    int i = blockIdx.x * 256 + threadIdx.x;
    ((float4*)g_wt)[i] = make_float4(0.f, 0.f, 0.f, 0.f);
}

// ===== prep: W_ss frag images (hi/lo) =====
__global__ void __launch_bounds__(256) prep_wss_kernel(const float* __restrict__ W_ss)
{
    int idx = blockIdx.x * 256 + threadIdx.x;    // 8192 uint4
    int lane = idx & 31, tp = (idx >> 5) & 31, ks = (idx >> 10) & 3, pass = idx >> 12;
    int gq = lane >> 2, tq = lane & 3;
    uint32_t r4[4];
#pragma unroll
    for (int r = 0; r < 4; r++) {
        int tile = 2 * tp + (r >> 1);
        int bsel = r & 1;
        int n = tile * 8 + gq;                   // W_ss col 0..511
        int e0 = ks * 16 + 2 * tq + 8 * bsel;    // W_ss row 0..63
        float v0 = W_ss[e0 * 512 + n], v1 = W_ss[(e0 + 1) * 512 + n];
        uint32_t h, l; split2(v0, v1, h, l);
        r4[r] = pass ? l : h;
    }
    g_Wss[idx] = make_uint4(r4[0], r4[1], r4[2], r4[3]);
}
// ===== prep: W_edges frag images (hi/lo), 4096 uint4 =====
__global__ void __launch_bounds__(256) prep_wed_kernel(const float* __restrict__ W_edges)
{
    int idx = blockIdx.x * 256 + threadIdx.x;    // 4096 uint4
    int lane = idx & 31, tp = (idx >> 5) & 3, ks = (idx >> 7) & 15, pass = idx >> 11;
    int gq = lane >> 2, tq = lane & 3;
    uint32_t r4[4];
#pragma unroll
    for (int r = 0; r < 4; r++) {
        int tile = 2 * tp + (r >> 1);
        int bsel = r & 1;
        int e = tile * 8 + gq;                   // W_edges col 0..63
        int c0 = ks * 16 + 2 * tq + 8 * bsel;    // W_edges row 0..255
        float v0 = W_edges[c0 * 64 + e], v1 = W_edges[(c0 + 1) * 64 + e];
        uint32_t h, l; split2(v0, v1, h, l);
        r4[r] = pass ? l : h;
    }
    g_Wed[idx] = make_uint4(r4[0], r4[1], r4[2], r4[3]);
}

// ===== generic small GEMM with bias (qkv + node projection), fp32 =====
__global__ void __launch_bounds__(256) gemm_bias_kernel(
    const float* __restrict__ A, const float* __restrict__ B,
    const float* __restrict__ bias, float* __restrict__ C, int M, int K, int N)
{
    __shared__ float sA[16][65];
    __shared__ float sB[16][64];
    const int nb = N >> 6;
    const int m0 = (blockIdx.x / nb) << 6, n0 = (blockIdx.x % nb) << 6;
    const int tm = threadIdx.x >> 4, tn = threadIdx.x & 15;
    float acc[4][4] = {};
    for (int kc = 0; kc < K; kc += 16) {
        const int tt = threadIdx.x;
        const int m = tt >> 2, k4 = (tt & 3) << 2;
        float4 a = *(const float4*)&A[(m0 + m) * K + kc + k4];
        sA[k4 + 0][m] = a.x; sA[k4 + 1][m] = a.y;
        sA[k4 + 2][m] = a.z; sA[k4 + 3][m] = a.w;
        const int kk = tt >> 4, n4 = (tt & 15) << 2;
        *(float4*)&sB[kk][n4] = *(const float4*)&B[(kc + kk) * N + n0 + n4];
        __syncthreads();
#pragma unroll
        for (int k2 = 0; k2 < 16; k2++) {
            float a0 = sA[k2][tm*4+0], a1 = sA[k2][tm*4+1];
            float a2 = sA[k2][tm*4+2], a3 = sA[k2][tm*4+3];
            float4 b4 = *(float4*)&sB[k2][tn*4];
            acc[0][0]+=a0*b4.x; acc[0][1]+=a0*b4.y; acc[0][2]+=a0*b4.z; acc[0][3]+=a0*b4.w;
            acc[1][0]+=a1*b4.x; acc[1][1]+=a1*b4.y; acc[1][2]+=a1*b4.z; acc[1][3]+=a1*b4.w;
            acc[2][0]+=a2*b4.x; acc[2][1]+=a2*b4.y; acc[2][2]+=a2*b4.z; acc[2][3]+=a2*b4.w;
            acc[3][0]+=a3*b4.x; acc[3][1]+=a3*b4.y; acc[3][2]+=a3*b4.z; acc[3][3]+=a3*b4.w;
        }
        __syncthreads();
    }
    float4 bb = *(const float4*)&bias[n0 + tn * 4];
#pragma unroll
    for (int i = 0; i < 4; i++)
        *(float4*)&C[(m0 + tm*4 + i) * N + n0 + tn*4] =
            make_float4(acc[i][0]+bb.x, acc[i][1]+bb.y, acc[i][2]+bb.z, acc[i][3]+bb.w);
}

// ===== main edge kernel: mma.sync bf16, CTA=(b,q), 8 warps 2Mx4N =====
__global__ void __launch_bounds__(256, 2) edge_mma_kernel(
    const float* __restrict__ edges, const float* __restrict__ b_ss,
    const float* __restrict__ b_edges, float* __restrict__ out_edges)
{
    extern __shared__ float sm[];
    float* sK   = sm;                    // [32][260]
    float* sE   = sm + 8320;             // [32][68]
    float* sQ   = sE + 2176;             // 256
    float* sBsh = sQ + 256;              // 256
    float* sBsc = sBsh + 256;            // 256
    float* sBed = sBsc + 256;            // 64
    uint32_t* sA2h = (uint32_t*)(sBed + 64);  // [32][132] bf16x2
    uint32_t* sA2l = sA2h + 4224;             // [32][132]

    const int tid = threadIdx.x;
    const int warp = tid >> 5, lane = tid & 31;
    const int wm = warp >> 2, wn = warp & 3;
    const int g = lane >> 2, t = lane & 3;
    const int b = blockIdx.x >> 8, q = blockIdx.x & 255;
    const int r0 = wm * 16 + g, r1 = r0 + 8;

    if (tid < 64)       *(float4*)&sQ[tid*4]   = *(const float4*)&g_QKV[(b*256+q)*768 + tid*4];
    else if (tid < 128) *(float4*)&sBsh[(tid-64)*4]  = *(const float4*)&b_ss[(tid-64)*4];
    else if (tid < 192) *(float4*)&sBsc[(tid-128)*4] = *(const float4*)&b_ss[256+(tid-128)*4];
    else if (tid < 208) *(float4*)&sBed[(tid-192)*4] = *(const float4*)&b_edges[(tid-192)*4];

    for (int kt = 0; kt < 8; kt++) {
        __syncthreads();
        // stage K rows [32][256] and edges tile [32][64]
#pragma unroll
        for (int i = 0; i < 8; i++) {
            int idx = tid + i * 256;
            int r = idx >> 6, c4 = idx & 63;
            *(float4*)&sK[r*260 + c4*4] =
                *(const float4*)&g_QKV[(b*256 + kt*32 + r)*768 + 256 + c4*4];
        }
#pragma unroll
        for (int i = 0; i < 2; i++) {
            int idx = tid + i * 256;
            int r = idx >> 4, e4 = idx & 15;
            *(float4*)&sE[r*68 + e4*4] =
                *(const float4*)&edges[(((size_t)(b*256+q))*256 + kt*32 + r)*64 + e4*4];
        }
        __syncthreads();

        // ---- GEMM1: shift(acc 0..7) + scale(acc 8..15), 3-pass bf16 ----
        float acc[16][4];
#pragma unroll
        for (int i = 0; i < 16; i++) { acc[i][0]=acc[i][1]=acc[i][2]=acc[i][3]=0.f; }
#pragma unroll
        for (int ks = 0; ks < 4; ks++) {
            uint32_t Ah[4], Al[4];
            {
                int e0 = ks * 16 + 2 * t;
                float2 v00 = *(float2*)&sE[r0*68 + e0];
                float2 v10 = *(float2*)&sE[r1*68 + e0];
                float2 v01 = *(float2*)&sE[r0*68 + e0 + 8];
                float2 v11 = *(float2*)&sE[r1*68 + e0 + 8];
                split2(v00.x, v00.y, Ah[0], Al[0]);
                split2(v10.x, v10.y, Ah[1], Al[1]);
                split2(v01.x, v01.y, Ah[2], Al[2]);
                split2(v11.x, v11.y, Ah[3], Al[3]);
            }
#pragma unroll
            for (int tpi = 0; tpi < 4; tpi++) {
                uint4 bh = g_Wss[((0*4 + ks)*32 + 4*wn + tpi)*32 + lane];        // shift hi
                mma16816(acc[2*tpi],   Ah, bh.x, bh.y);
                mma16816(acc[2*tpi+1], Ah, bh.z, bh.w);
                mma16816(acc[2*tpi],   Al, bh.x, bh.y);
                mma16816(acc[2*tpi+1], Al, bh.z, bh.w);
                uint4 bl = g_Wss[((1*4 + ks)*32 + 4*wn + tpi)*32 + lane];        // shift lo
                mma16816(acc[2*tpi],   Ah, bl.x, bl.y);
                mma16816(acc[2*tpi+1], Ah, bl.z, bl.w);
                uint4 ch = g_Wss[((0*4 + ks)*32 + 16 + 4*wn + tpi)*32 + lane];   // scale hi
                mma16816(acc[8+2*tpi],   Ah, ch.x, ch.y);
                mma16816(acc[8+2*tpi+1], Ah, ch.z, ch.w);
                mma16816(acc[8+2*tpi],   Al, ch.x, ch.y);
                mma16816(acc[8+2*tpi+1], Al, ch.z, ch.w);
                uint4 cl = g_Wss[((1*4 + ks)*32 + 16 + 4*wn + tpi)*32 + lane];   // scale lo
                mma16816(acc[8+2*tpi],   Ah, cl.x, cl.y);
                mma16816(acc[8+2*tpi+1], Ah, cl.z, cl.w);
            }
        }

        // ---- epilogue: ne, per-head logits, lrelu -> sA2 (bf16 hi/lo) ----
        float lg00 = 0.f, lg01 = 0.f, lg10 = 0.f, lg11 = 0.f;
#pragma unroll
        for (int lt = 0; lt < 8; lt++) {
            int c0 = wn * 64 + lt * 8 + 2 * t;
            float q0 = sQ[c0], q1 = sQ[c0+1];
            float ne00 = fmaf(q0 * sK[r0*260+c0],   acc[8+lt][0] + sBsc[c0],   q0 * sK[r0*260+c0])   + acc[lt][0] + sBsh[c0];
            float ne01 = fmaf(q1 * sK[r0*260+c0+1], acc[8+lt][1] + sBsc[c0+1], q1 * sK[r0*260+c0+1]) + acc[lt][1] + sBsh[c0+1];
            float ne10 = fmaf(q0 * sK[r1*260+c0],   acc[8+lt][2] + sBsc[c0],   q0 * sK[r1*260+c0])   + acc[lt][2] + sBsh[c0];
            float ne11 = fmaf(q1 * sK[r1*260+c0+1], acc[8+lt][3] + sBsc[c0+1], q1 * sK[r1*260+c0+1]) + acc[lt][3] + sBsh[c0+1];
            if (lt < 4) { lg00 += ne00 + ne01; lg10 += ne10 + ne11; }
            else        { lg01 += ne00 + ne01; lg11 += ne10 + ne11; }
            float p00 = ne00 > 0.f ? ne00 : 0.1f*ne00;
            float p01 = ne01 > 0.f ? ne01 : 0.1f*ne01;
            float p10 = ne10 > 0.f ? ne10 : 0.1f*ne10;
            float p11 = ne11 > 0.f ? ne11 : 0.1f*ne11;
            uint32_t h, l;
            int cp = wn * 32 + lt * 4 + t;
            split2(p00, p01, h, l); sA2h[r0*132 + cp] = h; sA2l[r0*132 + cp] = l;
            split2(p10, p11, h, l); sA2h[r1*132 + cp] = h; sA2l[r1*132 + cp] = l;
        }
        lg00 += __shfl_xor_sync(0xffffffffu, lg00, 1); lg00 += __shfl_xor_sync(0xffffffffu, lg00, 2);
        lg01 += __shfl_xor_sync(0xffffffffu, lg01, 1); lg01 += __shfl_xor_sync(0xffffffffu, lg01, 2);
        lg10 += __shfl_xor_sync(0xffffffffu, lg10, 1); lg10 += __shfl_xor_sync(0xffffffffu, lg10, 2);
        lg11 += __shfl_xor_sync(0xffffffffu, lg11, 1); lg11 += __shfl_xor_sync(0xffffffffu, lg11, 2);
        if (t == 0) {
            const float SC = 0.17677669529663687f;
            int kk = kt * 32;
            g_att[(((size_t)(b*8 + 2*wn+0))*256 + kk + r0)*256 + q] = lg00 * SC;
            g_att[(((size_t)(b*8 + 2*wn+1))*256 + kk + r0)*256 + q] = lg01 * SC;
            g_att[(((size_t)(b*8 + 2*wn+0))*256 + kk + r1)*256 + q] = lg10 * SC;
            g_att[(((size_t)(b*8 + 2*wn+1))*256 + kk + r1)*256 + q] = lg11 * SC;
        }
        __syncthreads();

        // ---- GEMM2: out = lrelu(ne)[32,256] @ W_edges[256,64], 3-pass ----
        float c2a[4] = {}, c2b[4] = {};
#pragma unroll
        for (int ks = 0; ks < 16; ks++) {
            uint32_t ah[4], al[4];
            ah[0] = sA2h[r0*132 + ks*8 + t];     al[0] = sA2l[r0*132 + ks*8 + t];
            ah[1] = sA2h[r1*132 + ks*8 + t];     al[1] = sA2l[r1*132 + ks*8 + t];
            ah[2] = sA2h[r0*132 + ks*8 + 4 + t]; al[2] = sA2l[r0*132 + ks*8 + 4 + t];
            ah[3] = sA2h[r1*132 + ks*8 + 4 + t]; al[3] = sA2l[r1*132 + ks*8 + 4 + t];
            uint4 bh = g_Wed[((0*16 + ks)*4 + wn)*32 + lane];
            uint4 bl = g_Wed[((1*16 + ks)*4 + wn)*32 + lane];
            mma16816(c2a, ah, bh.x, bh.y); mma16816(c2b, ah, bh.z, bh.w);
            mma16816(c2a, al, bh.x, bh.y); mma16816(c2b, al, bh.z, bh.w);
            mma16816(c2a, ah, bl.x, bl.y); mma16816(c2b, ah, bl.z, bl.w);
        }
        float* op = out_edges + (((size_t)(b*256+q))*256 + kt*32)*64;
        {
            int e0 = wn * 16 + 2 * t;
            *(float2*)&op[r0*64 + e0]     = make_float2(c2a[0] + sBed[e0],   c2a[1] + sBed[e0+1]);
            *(float2*)&op[r1*64 + e0]     = make_float2(c2a[2] + sBed[e0],   c2a[3] + sBed[e0+1]);
            *(float2*)&op[r0*64 + e0 + 8] = make_float2(c2b[0] + sBed[e0+8], c2b[1] + sBed[e0+9]);
            *(float2*)&op[r1*64 + e0 + 8] = make_float2(c2b[2] + sBed[e0+8], c2b[3] + sBed[e0+9]);
        }
    }
}

// ===== softmax over q for each (b,h,k) =====
__global__ void __launch_bounds__(256) softmax_q_kernel(float* __restrict__ lg)
{
    const int row = blockIdx.x * 8 + (threadIdx.x >> 5);
    const int lane = threadIdx.x & 31;
    float* p = lg + (size_t)row * 256;
    float4 v0 = *(float4*)&p[lane * 8];
    float4 v1 = *(float4*)&p[lane * 8 + 4];
    float v[8] = { v0.x, v0.y, v0.z, v0.w, v1.x, v1.y, v1.z, v1.w };
    float m = v[0];
#pragma unroll
    for (int i = 1; i < 8; i++) m = fmaxf(m, v[i]);
#pragma unroll
    for (int o = 16; o > 0; o >>= 1) m = fmaxf(m, __shfl_xor_sync(0xffffffffu, m, o));
    float s = 0.f;
#pragma unroll
    for (int i = 0; i < 8; i++) { v[i] = __expf(v[i] - m); s += v[i]; }
#pragma unroll
    for (int o = 16; o > 0; o >>= 1) s += __shfl_xor_sync(0xffffffffu, s, o);
    float inv = 1.f / s;
    *(float4*)&p[lane * 8]     = make_float4(v[0]*inv, v[1]*inv, v[2]*inv, v[3]*inv);
    *(float4*)&p[lane * 8 + 4] = make_float4(v[4]*inv, v[5]*inv, v[6]*inv, v[7]*inv);
}

// ===== attn @ V, k-split, atomics into zeroed g_wt =====
__global__ void __launch_bounds__(256) attnv2_kernel(const float* __restrict__ att)
{
    __shared__ float sv[32][32];   // unpadded: float4-aligned rows
    const int b = blockIdx.z >> 3, h = blockIdx.z & 7;
    const int kc = blockIdx.y, qc = blockIdx.x;
    const int dg = threadIdx.x >> 6, qq = threadIdx.x & 63;
    const int q = qc * 64 + qq;
    {
        int row = threadIdx.x >> 3, c4 = (threadIdx.x & 7) << 2;
        *(float4*)&sv[row][c4] =
            *(const float4*)&g_QKV[((b << 8) + kc * 32 + row) * 768 + 512 + h * 32 + c4];
    }
    __syncthreads();
    const float* ap = att + (((size_t)((b << 3) + h)) * 256 + kc * 32) * 256 + q;
    float acc[8] = {};
#pragma unroll
    for (int kk = 0; kk < 32; kk++) {
        float a = ap[(size_t)kk * 256];
        float4 u0 = *(float4*)&sv[kk][dg * 8];
        float4 u1 = *(float4*)&sv[kk][dg * 8 + 4];
        acc[0]+=a*u0.x; acc[1]+=a*u0.y; acc[2]+=a*u0.z; acc[3]+=a*u0.w;
        acc[4]+=a*u1.x; acc[5]+=a*u1.y; acc[6]+=a*u1.z; acc[7]+=a*u1.w;
    }
    float* wp = &g_wt[((b << 8) + q) * 256 + h * 32 + dg * 8];
#pragma unroll
    for (int j = 0; j < 8; j++) atomicAdd(wp + j, acc[j]);
}

// ===== launch =====
extern "C" void kernel_launch(void* const* d_in, const int* in_sizes, int n_in,
                              void* d_out, int out_size)
{
    const float* nodes   = (const float*)d_in[0];
    const float* edges   = (const float*)d_in[1];
    const float* W_qkv   = (const float*)d_in[2];
    const float* b_qkv   = (const float*)d_in[3];
    const float* W_ss    = (const float*)d_in[4];
    const float* b_ss    = (const float*)d_in[5];
    const float* W_nodes = (const float*)d_in[6];
    const float* b_nodes = (const float*)d_in[7];
    const float* W_edges = (const float*)d_in[8];
    const float* b_edges = (const float*)d_in[9];

    float* out_nodes = (float*)d_out;
    float* out_edges = out_nodes + 512 * 256;

    float *qkvp = nullptr, *attp = nullptr, *wtp = nullptr;
    cudaGetSymbolAddress((void**)&qkvp, g_QKV);
    cudaGetSymbolAddress((void**)&attp, g_att);
    cudaGetSymbolAddress((void**)&wtp, g_wt);

    const int EDGE_SMEM = 19776 * sizeof(float);   // 79104 B
    cudaFuncSetAttribute(edge_mma_kernel,
                         cudaFuncAttributeMaxDynamicSharedMemorySize, EDGE_SMEM);

    zero_wt_kernel<<<128, 256>>>();
    prep_wss_kernel<<<32, 256>>>(W_ss);
    prep_wed_kernel<<<16, 256>>>(W_edges);
    gemm_bias_kernel<<<(512/64)*(768/64), 256>>>(nodes, W_qkv, b_qkv, qkvp, 512, 256, 768);
    edge_mma_kernel<<<512, 256, EDGE_SMEM>>>(edges, b_ss, b_edges, out_edges);
    softmax_q_kernel<<<512, 256>>>(attp);
    attnv2_kernel<<<dim3(4, 8, 16), 256>>>(attp);
    gemm_bias_kernel<<<(512/64)*(256/64), 256>>>(wtp, W_nodes, b_nodes, out_nodes, 512, 256, 256);
}

// round 8
// speedup vs baseline: 2.5839x; 1.0691x over previous
#include <cuda_runtime.h>
#include <cuda_bf16.h>
#include <cstdint>

// ---------------------------------------------------------------------------
// mma.sync bf16 3-pass implementation. B=2,N=256,NODE=256,EDGE=64,H=8,D=32.
// R8: edge kernel drops K-tile smem staging (direct L1 LDG in epilogue),
//     double-buffers the edges tile; gemm_bias re-tiled 32x64 for 2x blocks.
// ---------------------------------------------------------------------------

__device__ __forceinline__ void mma16816(float c[4], const uint32_t a[4],
                                         uint32_t b0, uint32_t b1) {
    asm volatile("mma.sync.aligned.m16n8k16.row.col.f32.bf16.bf16.f32 "
        "{%0,%1,%2,%3},{%4,%5,%6,%7},{%8,%9},{%0,%1,%2,%3};"
        : "+f"(c[0]), "+f"(c[1]), "+f"(c[2]), "+f"(c[3])
        : "r"(a[0]), "r"(a[1]), "r"(a[2]), "r"(a[3]), "r"(b0), "r"(b1));
}
__device__ __forceinline__ void split2(float v0, float v1, uint32_t& h, uint32_t& l) {
    __nv_bfloat162 hh = __floats2bfloat162_rn(v0, v1);
    float h0 = __bfloat162float(hh.x), h1 = __bfloat162float(hh.y);
    __nv_bfloat162 ll = __floats2bfloat162_rn(v0 - h0, v1 - h1);
    h = *(uint32_t*)&hh; l = *(uint32_t*)&ll;
}

// ===== scratch =====
__device__ float g_QKV[512 * 768];          // [b*256+n][768] q|k|v
__device__ float g_att[2 * 8 * 256 * 256];  // [b][h][k][q]
__device__ float g_wt[512 * 256];
__device__ uint4 g_Wss[8192];   // [pass2][ks4][tp32][lane32] frag-linear bf16x2
__device__ uint4 g_Wed[4096];   // [pass2][ks16][tp4][lane32]

__global__ void __launch_bounds__(256) zero_wt_kernel()
{
    int i = blockIdx.x * 256 + threadIdx.x;
    ((float4*)g_wt)[i] = make_float4(0.f, 0.f, 0.f, 0.f);
}

// ===== prep: W_ss frag images (hi/lo) =====
__global__ void __launch_bounds__(256) prep_wss_kernel(const float* __restrict__ W_ss)
{
    int idx = blockIdx.x * 256 + threadIdx.x;    // 8192 uint4
    int lane = idx & 31, tp = (idx >> 5) & 31, ks = (idx >> 10) & 3, pass = idx >> 12;
    int gq = lane >> 2, tq = lane & 3;
    uint32_t r4[4];
#pragma unroll
    for (int r = 0; r < 4; r++) {
        int tile = 2 * tp + (r >> 1);
        int bsel = r & 1;
        int n = tile * 8 + gq;
        int e0 = ks * 16 + 2 * tq + 8 * bsel;
        float v0 = W_ss[e0 * 512 + n], v1 = W_ss[(e0 + 1) * 512 + n];
        uint32_t h, l; split2(v0, v1, h, l);
        r4[r] = pass ? l : h;
    }
    g_Wss[idx] = make_uint4(r4[0], r4[1], r4[2], r4[3]);
}
// ===== prep: W_edges frag images (hi/lo) =====
__global__ void __launch_bounds__(256) prep_wed_kernel(const float* __restrict__ W_edges)
{
    int idx = blockIdx.x * 256 + threadIdx.x;    // 4096 uint4
    int lane = idx & 31, tp = (idx >> 5) & 3, ks = (idx >> 7) & 15, pass = idx >> 11;
    int gq = lane >> 2, tq = lane & 3;
    uint32_t r4[4];
#pragma unroll
    for (int r = 0; r < 4; r++) {
        int tile = 2 * tp + (r >> 1);
        int bsel = r & 1;
        int e = tile * 8 + gq;
        int c0 = ks * 16 + 2 * tq + 8 * bsel;
        float v0 = W_edges[c0 * 64 + e], v1 = W_edges[(c0 + 1) * 64 + e];
        uint32_t h, l; split2(v0, v1, h, l);
        r4[r] = pass ? l : h;
    }
    g_Wed[idx] = make_uint4(r4[0], r4[1], r4[2], r4[3]);
}

// ===== small GEMM with bias, 32x64 tiles (more blocks, latency-bound fix) =====
__global__ void __launch_bounds__(256) gemm_bias_kernel(
    const float* __restrict__ A, const float* __restrict__ B,
    const float* __restrict__ bias, float* __restrict__ C, int M, int K, int N)
{
    __shared__ float sA[16][33];   // [k][m] 32 rows
    __shared__ float sB[16][64];
    const int nb = N >> 6;
    const int m0 = (blockIdx.x / nb) << 5, n0 = (blockIdx.x % nb) << 6;
    const int tm = threadIdx.x >> 4, tn = threadIdx.x & 15;
    float acc[2][4] = {};
    for (int kc = 0; kc < K; kc += 16) {
        const int tt = threadIdx.x;
        if (tt < 128) {
            const int m = tt >> 2, k4 = (tt & 3) << 2;
            float4 a = *(const float4*)&A[(m0 + m) * K + kc + k4];
            sA[k4 + 0][m] = a.x; sA[k4 + 1][m] = a.y;
            sA[k4 + 2][m] = a.z; sA[k4 + 3][m] = a.w;
        }
        const int kk = tt >> 4, n4 = (tt & 15) << 2;
        *(float4*)&sB[kk][n4] = *(const float4*)&B[(kc + kk) * N + n0 + n4];
        __syncthreads();
#pragma unroll
        for (int k2 = 0; k2 < 16; k2++) {
            float a0 = sA[k2][tm*2+0], a1 = sA[k2][tm*2+1];
            float4 b4 = *(float4*)&sB[k2][tn*4];
            acc[0][0]+=a0*b4.x; acc[0][1]+=a0*b4.y; acc[0][2]+=a0*b4.z; acc[0][3]+=a0*b4.w;
            acc[1][0]+=a1*b4.x; acc[1][1]+=a1*b4.y; acc[1][2]+=a1*b4.z; acc[1][3]+=a1*b4.w;
        }
        __syncthreads();
    }
    float4 bb = *(const float4*)&bias[n0 + tn * 4];
#pragma unroll
    for (int i = 0; i < 2; i++)
        *(float4*)&C[(m0 + tm*2 + i) * N + n0 + tn*4] =
            make_float4(acc[i][0]+bb.x, acc[i][1]+bb.y, acc[i][2]+bb.z, acc[i][3]+bb.w);
}

// ===== main edge kernel: mma.sync bf16, CTA=(b,q), 8 warps 2Mx4N =====
__global__ void __launch_bounds__(256, 2) edge_mma_kernel(
    const float* __restrict__ edges, const float* __restrict__ b_ss,
    const float* __restrict__ b_edges, float* __restrict__ out_edges)
{
    extern __shared__ float sm[];
    float* sE0  = sm;                    // [32][68] buffer 0
    float* sE1  = sm + 2176;             // [32][68] buffer 1
    float* sQ   = sm + 4352;             // 256
    float* sBsh = sQ + 256;              // 256
    float* sBsc = sBsh + 256;            // 256
    float* sBed = sBsc + 256;            // 64
    uint32_t* sA2h = (uint32_t*)(sBed + 64);  // [32][132] bf16x2
    uint32_t* sA2l = sA2h + 4224;             // [32][132]

    const int tid = threadIdx.x;
    const int warp = tid >> 5, lane = tid & 31;
    const int wm = warp >> 2, wn = warp & 3;
    const int g = lane >> 2, t = lane & 3;
    const int b = blockIdx.x >> 8, q = blockIdx.x & 255;
    const int r0 = wm * 16 + g, r1 = r0 + 8;

    // per-thread edge staging coords (2 float4 per thread per 32x64 tile)
    const int er0 = tid >> 4,         ec0 = (tid & 15) << 2;
    const int er1 = (tid + 256) >> 4, ec1 = ec0;
    const float* ep = edges + (((size_t)(b * 256 + q)) * 256) * 64;

    if (tid < 64)       *(float4*)&sQ[tid*4]   = *(const float4*)&g_QKV[(b*256+q)*768 + tid*4];
    else if (tid < 128) *(float4*)&sBsh[(tid-64)*4]  = *(const float4*)&b_ss[(tid-64)*4];
    else if (tid < 192) *(float4*)&sBsc[(tid-128)*4] = *(const float4*)&b_ss[256+(tid-128)*4];
    else if (tid < 208) *(float4*)&sBed[(tid-192)*4] = *(const float4*)&b_edges[(tid-192)*4];

    // preload tile 0
    {
        float4 v0 = *(const float4*)(ep + (size_t)er0 * 64 + ec0);
        float4 v1 = *(const float4*)(ep + (size_t)er1 * 64 + ec1);
        *(float4*)&sE0[er0*68 + ec0] = v0;
        *(float4*)&sE1[0] = v0;  // dummy init (overwritten); keeps compiler honest
        *(float4*)&sE0[er1*68 + ec1] = v1;
    }
    __syncthreads();

    for (int kt = 0; kt < 8; kt++) {
        float* sEc = (kt & 1) ? sE1 : sE0;
        float* sEn = (kt & 1) ? sE0 : sE1;

        // prefetch next tile (wrapped index on last iter; store is discarded)
        int ktn = (kt + 1) & 7;
        float4 pf0 = *(const float4*)(ep + (size_t)(ktn*32 + er0) * 64 + ec0);
        float4 pf1 = *(const float4*)(ep + (size_t)(ktn*32 + er1) * 64 + ec1);

        // ---- GEMM1: shift(acc 0..7) + scale(acc 8..15), 3-pass bf16 ----
        float acc[16][4];
#pragma unroll
        for (int i = 0; i < 16; i++) { acc[i][0]=acc[i][1]=acc[i][2]=acc[i][3]=0.f; }
#pragma unroll
        for (int ks = 0; ks < 4; ks++) {
            uint32_t Ah[4], Al[4];
            {
                int e0 = ks * 16 + 2 * t;
                float2 v00 = *(float2*)&sEc[r0*68 + e0];
                float2 v10 = *(float2*)&sEc[r1*68 + e0];
                float2 v01 = *(float2*)&sEc[r0*68 + e0 + 8];
                float2 v11 = *(float2*)&sEc[r1*68 + e0 + 8];
                split2(v00.x, v00.y, Ah[0], Al[0]);
                split2(v10.x, v10.y, Ah[1], Al[1]);
                split2(v01.x, v01.y, Ah[2], Al[2]);
                split2(v11.x, v11.y, Ah[3], Al[3]);
            }
#pragma unroll
            for (int tpi = 0; tpi < 4; tpi++) {
                uint4 bh = g_Wss[((0*4 + ks)*32 + 4*wn + tpi)*32 + lane];
                mma16816(acc[2*tpi],   Ah, bh.x, bh.y);
                mma16816(acc[2*tpi+1], Ah, bh.z, bh.w);
                mma16816(acc[2*tpi],   Al, bh.x, bh.y);
                mma16816(acc[2*tpi+1], Al, bh.z, bh.w);
                uint4 bl = g_Wss[((1*4 + ks)*32 + 4*wn + tpi)*32 + lane];
                mma16816(acc[2*tpi],   Ah, bl.x, bl.y);
                mma16816(acc[2*tpi+1], Ah, bl.z, bl.w);
                uint4 ch = g_Wss[((0*4 + ks)*32 + 16 + 4*wn + tpi)*32 + lane];
                mma16816(acc[8+2*tpi],   Ah, ch.x, ch.y);
                mma16816(acc[8+2*tpi+1], Ah, ch.z, ch.w);
                mma16816(acc[8+2*tpi],   Al, ch.x, ch.y);
                mma16816(acc[8+2*tpi+1], Al, ch.z, ch.w);
                uint4 cl = g_Wss[((1*4 + ks)*32 + 16 + 4*wn + tpi)*32 + lane];
                mma16816(acc[8+2*tpi],   Ah, cl.x, cl.y);
                mma16816(acc[8+2*tpi+1], Ah, cl.z, cl.w);
            }
        }

        // store prefetched edges into the other buffer (no reader conflict:
        // readers of sEn finished before last iteration's trailing sync)
        *(float4*)&sEn[er0*68 + ec0] = pf0;
        *(float4*)&sEn[er1*68 + ec1] = pf1;

        // ---- epilogue: ne, logits, lrelu -> sA2 (K read direct from L1) ----
        const float* kr0 = &g_QKV[(b*256 + kt*32 + r0)*768 + 256];
        const float* kr1 = &g_QKV[(b*256 + kt*32 + r1)*768 + 256];
        float lg00 = 0.f, lg01 = 0.f, lg10 = 0.f, lg11 = 0.f;
#pragma unroll
        for (int lt = 0; lt < 8; lt++) {
            int c0 = wn * 64 + lt * 8 + 2 * t;
            float2 k0v = *(const float2*)(kr0 + c0);
            float2 k1v = *(const float2*)(kr1 + c0);
            float q0 = sQ[c0], q1 = sQ[c0+1];
            float qk00 = q0 * k0v.x, qk01 = q1 * k0v.y;
            float qk10 = q0 * k1v.x, qk11 = q1 * k1v.y;
            float ne00 = fmaf(qk00, acc[8+lt][0] + sBsc[c0],   qk00) + acc[lt][0] + sBsh[c0];
            float ne01 = fmaf(qk01, acc[8+lt][1] + sBsc[c0+1], qk01) + acc[lt][1] + sBsh[c0+1];
            float ne10 = fmaf(qk10, acc[8+lt][2] + sBsc[c0],   qk10) + acc[lt][2] + sBsh[c0];
            float ne11 = fmaf(qk11, acc[8+lt][3] + sBsc[c0+1], qk11) + acc[lt][3] + sBsh[c0+1];
            if (lt < 4) { lg00 += ne00 + ne01; lg10 += ne10 + ne11; }
            else        { lg01 += ne00 + ne01; lg11 += ne10 + ne11; }
            float p00 = ne00 > 0.f ? ne00 : 0.1f*ne00;
            float p01 = ne01 > 0.f ? ne01 : 0.1f*ne01;
            float p10 = ne10 > 0.f ? ne10 : 0.1f*ne10;
            float p11 = ne11 > 0.f ? ne11 : 0.1f*ne11;
            uint32_t h, l;
            int cp = wn * 32 + lt * 4 + t;
            split2(p00, p01, h, l); sA2h[r0*132 + cp] = h; sA2l[r0*132 + cp] = l;
            split2(p10, p11, h, l); sA2h[r1*132 + cp] = h; sA2l[r1*132 + cp] = l;
        }
        lg00 += __shfl_xor_sync(0xffffffffu, lg00, 1); lg00 += __shfl_xor_sync(0xffffffffu, lg00, 2);
        lg01 += __shfl_xor_sync(0xffffffffu, lg01, 1); lg01 += __shfl_xor_sync(0xffffffffu, lg01, 2);
        lg10 += __shfl_xor_sync(0xffffffffu, lg10, 1); lg10 += __shfl_xor_sync(0xffffffffu, lg10, 2);
        lg11 += __shfl_xor_sync(0xffffffffu, lg11, 1); lg11 += __shfl_xor_sync(0xffffffffu, lg11, 2);
        if (t == 0) {
            const float SC = 0.17677669529663687f;
            int kk = kt * 32;
            g_att[(((size_t)(b*8 + 2*wn+0))*256 + kk + r0)*256 + q] = lg00 * SC;
            g_att[(((size_t)(b*8 + 2*wn+1))*256 + kk + r0)*256 + q] = lg01 * SC;
            g_att[(((size_t)(b*8 + 2*wn+0))*256 + kk + r1)*256 + q] = lg10 * SC;
            g_att[(((size_t)(b*8 + 2*wn+1))*256 + kk + r1)*256 + q] = lg11 * SC;
        }
        __syncthreads();

        // ---- GEMM2: out = lrelu(ne)[32,256] @ W_edges[256,64], 3-pass ----
        float c2a[4] = {}, c2b[4] = {};
#pragma unroll
        for (int ks = 0; ks < 16; ks++) {
            uint32_t ah[4], al[4];
            ah[0] = sA2h[r0*132 + ks*8 + t];     al[0] = sA2l[r0*132 + ks*8 + t];
            ah[1] = sA2h[r1*132 + ks*8 + t];     al[1] = sA2l[r1*132 + ks*8 + t];
            ah[2] = sA2h[r0*132 + ks*8 + 4 + t]; al[2] = sA2l[r0*132 + ks*8 + 4 + t];
            ah[3] = sA2h[r1*132 + ks*8 + 4 + t]; al[3] = sA2l[r1*132 + ks*8 + 4 + t];
            uint4 bh = g_Wed[((0*16 + ks)*4 + wn)*32 + lane];
            uint4 bl = g_Wed[((1*16 + ks)*4 + wn)*32 + lane];
            mma16816(c2a, ah, bh.x, bh.y); mma16816(c2b, ah, bh.z, bh.w);
            mma16816(c2a, al, bh.x, bh.y); mma16816(c2b, al, bh.z, bh.w);
            mma16816(c2a, ah, bl.x, bl.y); mma16816(c2b, ah, bl.z, bl.w);
        }
        float* op = out_edges + (((size_t)(b*256+q))*256 + kt*32)*64;
        {
            int e0 = wn * 16 + 2 * t;
            *(float2*)&op[r0*64 + e0]     = make_float2(c2a[0] + sBed[e0],   c2a[1] + sBed[e0+1]);
            *(float2*)&op[r1*64 + e0]     = make_float2(c2a[2] + sBed[e0],   c2a[3] + sBed[e0+1]);
            *(float2*)&op[r0*64 + e0 + 8] = make_float2(c2b[0] + sBed[e0+8], c2b[1] + sBed[e0+9]);
            *(float2*)&op[r1*64 + e0 + 8] = make_float2(c2b[2] + sBed[e0+8], c2b[3] + sBed[e0+9]);
        }
        __syncthreads();   // sA2 reuse + sEn visibility for next GEMM1
    }
}

// ===== softmax over q for each (b,h,k) =====
__global__ void __launch_bounds__(256) softmax_q_kernel(float* __restrict__ lg)
{
    const int row = blockIdx.x * 8 + (threadIdx.x >> 5);
    const int lane = threadIdx.x & 31;
    float* p = lg + (size_t)row * 256;
    float4 v0 = *(float4*)&p[lane * 8];
    float4 v1 = *(float4*)&p[lane * 8 + 4];
    float v[8] = { v0.x, v0.y, v0.z, v0.w, v1.x, v1.y, v1.z, v1.w };
    float m = v[0];
#pragma unroll
    for (int i = 1; i < 8; i++) m = fmaxf(m, v[i]);
#pragma unroll
    for (int o = 16; o > 0; o >>= 1) m = fmaxf(m, __shfl_xor_sync(0xffffffffu, m, o));
    float s = 0.f;
#pragma unroll
    for (int i = 0; i < 8; i++) { v[i] = __expf(v[i] - m); s += v[i]; }
#pragma unroll
    for (int o = 16; o > 0; o >>= 1) s += __shfl_xor_sync(0xffffffffu, s, o);
    float inv = 1.f / s;
    *(float4*)&p[lane * 8]     = make_float4(v[0]*inv, v[1]*inv, v[2]*inv, v[3]*inv);
    *(float4*)&p[lane * 8 + 4] = make_float4(v[4]*inv, v[5]*inv, v[6]*inv, v[7]*inv);
}

// ===== attn @ V, k-split, atomics into zeroed g_wt =====
__global__ void __launch_bounds__(256) attnv2_kernel(const float* __restrict__ att)
{
    __shared__ float sv[32][32];
    const int b = blockIdx.z >> 3, h = blockIdx.z & 7;
    const int kc = blockIdx.y, qc = blockIdx.x;
    const int dg = threadIdx.x >> 6, qq = threadIdx.x & 63;
    const int q = qc * 64 + qq;
    {
        int row = threadIdx.x >> 3, c4 = (threadIdx.x & 7) << 2;
        *(float4*)&sv[row][c4] =
            *(const float4*)&g_QKV[((b << 8) + kc * 32 + row) * 768 + 512 + h * 32 + c4];
    }
    __syncthreads();
    const float* ap = att + (((size_t)((b << 3) + h)) * 256 + kc * 32) * 256 + q;
    float acc[8] = {};
#pragma unroll
    for (int kk = 0; kk < 32; kk++) {
        float a = ap[(size_t)kk * 256];
        float4 u0 = *(float4*)&sv[kk][dg * 8];
        float4 u1 = *(float4*)&sv[kk][dg * 8 + 4];
        acc[0]+=a*u0.x; acc[1]+=a*u0.y; acc[2]+=a*u0.z; acc[3]+=a*u0.w;
        acc[4]+=a*u1.x; acc[5]+=a*u1.y; acc[6]+=a*u1.z; acc[7]+=a*u1.w;
    }
    float* wp = &g_wt[((b << 8) + q) * 256 + h * 32 + dg * 8];
#pragma unroll
    for (int j = 0; j < 8; j++) atomicAdd(wp + j, acc[j]);
}

// ===== launch =====
extern "C" void kernel_launch(void* const* d_in, const int* in_sizes, int n_in,
                              void* d_out, int out_size)
{
    const float* nodes   = (const float*)d_in[0];
    const float* edges   = (const float*)d_in[1];
    const float* W_qkv   = (const float*)d_in[2];
    const float* b_qkv   = (const float*)d_in[3];
    const float* W_ss    = (const float*)d_in[4];
    const float* b_ss    = (const float*)d_in[5];
    const float* W_nodes = (const float*)d_in[6];
    const float* b_nodes = (const float*)d_in[7];
    const float* W_edges = (const float*)d_in[8];
    const float* b_edges = (const float*)d_in[9];

    float* out_nodes = (float*)d_out;
    float* out_edges = out_nodes + 512 * 256;

    float *qkvp = nullptr, *attp = nullptr, *wtp = nullptr;
    cudaGetSymbolAddress((void**)&qkvp, g_QKV);
    cudaGetSymbolAddress((void**)&attp, g_att);
    cudaGetSymbolAddress((void**)&wtp, g_wt);

    const int EDGE_SMEM = (4352 + 832 + 8448) * sizeof(float);   // 54528 B
    cudaFuncSetAttribute(edge_mma_kernel,
                         cudaFuncAttributeMaxDynamicSharedMemorySize, EDGE_SMEM);

    zero_wt_kernel<<<128, 256>>>();
    prep_wss_kernel<<<32, 256>>>(W_ss);
    prep_wed_kernel<<<16, 256>>>(W_edges);
    gemm_bias_kernel<<<(512/32)*(768/64), 256>>>(nodes, W_qkv, b_qkv, qkvp, 512, 256, 768);
    edge_mma_kernel<<<512, 256, EDGE_SMEM>>>(edges, b_ss, b_edges, out_edges);
    softmax_q_kernel<<<512, 256>>>(attp);
    attnv2_kernel<<<dim3(4, 8, 16), 256>>>(attp);
    gemm_bias_kernel<<<(512/32)*(256/64), 256>>>(wtp, W_nodes, b_nodes, out_nodes, 512, 256, 256);
}

// round 9
// speedup vs baseline: 3.1500x; 1.2191x over previous
#include <cuda_runtime.h>
#include <cuda_fp16.h>
#include <cstdint>

// ---------------------------------------------------------------------------
// mma.sync fp16 2-pass implementation. B=2,N=256,NODE=256,EDGE=64,H=8,D=32.
// A split hi/lo fp16 (exact to 2^-22); B rounded to fp16 hi only.
// Error = A@(B-Bh) ~ 1.5e-4 rel (validated error model: bf16 1-pass predicted
// 1.7e-3, observed 1.667e-3). HMMA count 9.44M -> 6.29M.
// ---------------------------------------------------------------------------

__device__ __forceinline__ void mma16816h(float c[4], const uint32_t a[4],
                                          uint32_t b0, uint32_t b1) {
    asm volatile("mma.sync.aligned.m16n8k16.row.col.f32.f16.f16.f32 "
        "{%0,%1,%2,%3},{%4,%5,%6,%7},{%8,%9},{%0,%1,%2,%3};"
        : "+f"(c[0]), "+f"(c[1]), "+f"(c[2]), "+f"(c[3])
        : "r"(a[0]), "r"(a[1]), "r"(a[2]), "r"(a[3]), "r"(b0), "r"(b1));
}
// pack (v0,v1) as fp16 hi image + fp16 residual lo image (hi+lo = v to 2^-22)
__device__ __forceinline__ void split2h(float v0, float v1, uint32_t& h, uint32_t& l) {
    __half2 hh = __floats2half2_rn(v0, v1);
    float h0 = __low2float(hh), h1 = __high2float(hh);
    __half2 ll = __floats2half2_rn(v0 - h0, v1 - h1);
    h = *(uint32_t*)&hh; l = *(uint32_t*)&ll;
}
__device__ __forceinline__ uint32_t pack2h(float v0, float v1) {
    __half2 hh = __floats2half2_rn(v0, v1);
    return *(uint32_t*)&hh;
}

// ===== scratch =====
__device__ float g_QKV[512 * 768];          // [b*256+n][768] q|k|v
__device__ float g_att[2 * 8 * 256 * 256];  // [b][h][k][q]
__device__ float g_wt[512 * 256];
__device__ uint4 g_Wss[4096];   // [ks4][tp32][lane32] frag-linear fp16x2 (hi only)
__device__ uint4 g_Wed[2048];   // [ks16][tp4][lane32]

__global__ void __launch_bounds__(256) zero_wt_kernel()
{
    int i = blockIdx.x * 256 + threadIdx.x;
    ((float4*)g_wt)[i] = make_float4(0.f, 0.f, 0.f, 0.f);
}

// ===== prep: W_ss frag image (fp16 hi) =====
__global__ void __launch_bounds__(256) prep_wss_kernel(const float* __restrict__ W_ss)
{
    int idx = blockIdx.x * 256 + threadIdx.x;    // 4096 uint4
    int lane = idx & 31, tp = (idx >> 5) & 31, ks = idx >> 10;
    int gq = lane >> 2, tq = lane & 3;
    uint32_t r4[4];
#pragma unroll
    for (int r = 0; r < 4; r++) {
        int tile = 2 * tp + (r >> 1);
        int bsel = r & 1;
        int n = tile * 8 + gq;                   // W_ss col 0..511
        int e0 = ks * 16 + 2 * tq + 8 * bsel;    // W_ss row 0..63
        r4[r] = pack2h(W_ss[e0 * 512 + n], W_ss[(e0 + 1) * 512 + n]);
    }
    g_Wss[idx] = make_uint4(r4[0], r4[1], r4[2], r4[3]);
}
// ===== prep: W_edges frag image (fp16 hi) =====
__global__ void __launch_bounds__(256) prep_wed_kernel(const float* __restrict__ W_edges)
{
    int idx = blockIdx.x * 256 + threadIdx.x;    // 2048 uint4
    int lane = idx & 31, tp = (idx >> 5) & 3, ks = idx >> 7;
    int gq = lane >> 2, tq = lane & 3;
    uint32_t r4[4];
#pragma unroll
    for (int r = 0; r < 4; r++) {
        int tile = 2 * tp + (r >> 1);
        int bsel = r & 1;
        int e = tile * 8 + gq;                   // W_edges col 0..63
        int c0 = ks * 16 + 2 * tq + 8 * bsel;    // W_edges row 0..255
        r4[r] = pack2h(W_edges[c0 * 64 + e], W_edges[(c0 + 1) * 64 + e]);
    }
    g_Wed[idx] = make_uint4(r4[0], r4[1], r4[2], r4[3]);
}

// ===== small GEMM with bias, 32x64 tiles, double-buffered k-loop =====
__global__ void __launch_bounds__(256) gemm_bias_kernel(
    const float* __restrict__ A, const float* __restrict__ B,
    const float* __restrict__ bias, float* __restrict__ C, int M, int K, int N)
{
    __shared__ float sA[2][16][33];
    __shared__ float sB[2][16][64];
    const int nb = N >> 6;
    const int m0 = (blockIdx.x / nb) << 5, n0 = (blockIdx.x % nb) << 6;
    const int tm = threadIdx.x >> 4, tn = threadIdx.x & 15;
    const int tt = threadIdx.x;
    const int am = tt >> 2, ak4 = (tt & 3) << 2;     // tt<128 loads A
    const int bk = tt >> 4, bn4 = (tt & 15) << 2;
    const int nk = K >> 4;

    float4 aR, bR;
    if (tt < 128) aR = *(const float4*)&A[(m0 + am) * K + ak4];
    bR = *(const float4*)&B[bk * N + n0 + bn4];
    if (tt < 128) {
        sA[0][ak4+0][am] = aR.x; sA[0][ak4+1][am] = aR.y;
        sA[0][ak4+2][am] = aR.z; sA[0][ak4+3][am] = aR.w;
    }
    *(float4*)&sB[0][bk][bn4] = bR;
    __syncthreads();

    float acc[2][4] = {};
    for (int kc = 0; kc < nk; kc++) {
        const int cur = kc & 1;
        if (kc + 1 < nk) {
            if (tt < 128) aR = *(const float4*)&A[(m0 + am) * K + (kc+1)*16 + ak4];
            bR = *(const float4*)&B[((kc+1)*16 + bk) * N + n0 + bn4];
        }
#pragma unroll
        for (int k2 = 0; k2 < 16; k2++) {
            float a0 = sA[cur][k2][tm*2+0], a1 = sA[cur][k2][tm*2+1];
            float4 b4 = *(float4*)&sB[cur][k2][tn*4];
            acc[0][0]+=a0*b4.x; acc[0][1]+=a0*b4.y; acc[0][2]+=a0*b4.z; acc[0][3]+=a0*b4.w;
            acc[1][0]+=a1*b4.x; acc[1][1]+=a1*b4.y; acc[1][2]+=a1*b4.z; acc[1][3]+=a1*b4.w;
        }
        if (kc + 1 < nk) {
            const int nxt = cur ^ 1;
            if (tt < 128) {
                sA[nxt][ak4+0][am] = aR.x; sA[nxt][ak4+1][am] = aR.y;
                sA[nxt][ak4+2][am] = aR.z; sA[nxt][ak4+3][am] = aR.w;
            }
            *(float4*)&sB[nxt][bk][bn4] = bR;
        }
        __syncthreads();
    }
    float4 bb = *(const float4*)&bias[n0 + tn * 4];
#pragma unroll
    for (int i = 0; i < 2; i++)
        *(float4*)&C[(m0 + tm*2 + i) * N + n0 + tn*4] =
            make_float4(acc[i][0]+bb.x, acc[i][1]+bb.y, acc[i][2]+bb.z, acc[i][3]+bb.w);
}

// ===== main edge kernel: mma.sync fp16 2-pass, CTA=(b,q), 8 warps 2Mx4N =====
__global__ void __launch_bounds__(256, 2) edge_mma_kernel(
    const float* __restrict__ edges, const float* __restrict__ b_ss,
    const float* __restrict__ b_edges, float* __restrict__ out_edges)
{
    extern __shared__ float sm[];
    float* sE0  = sm;                    // [32][68] buffer 0
    float* sE1  = sm + 2176;             // [32][68] buffer 1
    float* sQ   = sm + 4352;             // 256
    float* sBsh = sQ + 256;              // 256
    float* sBsc = sBsh + 256;            // 256
    float* sBed = sBsc + 256;            // 64
    uint32_t* sA2h = (uint32_t*)(sBed + 64);  // [32][132] fp16x2
    uint32_t* sA2l = sA2h + 4224;             // [32][132]

    const int tid = threadIdx.x;
    const int warp = tid >> 5, lane = tid & 31;
    const int wm = warp >> 2, wn = warp & 3;
    const int g = lane >> 2, t = lane & 3;
    const int b = blockIdx.x >> 8, q = blockIdx.x & 255;
    const int r0 = wm * 16 + g, r1 = r0 + 8;

    const int er0 = tid >> 4,         ec0 = (tid & 15) << 2;
    const int er1 = (tid + 256) >> 4, ec1 = ec0;
    const float* ep = edges + (((size_t)(b * 256 + q)) * 256) * 64;

    if (tid < 64)       *(float4*)&sQ[tid*4]   = *(const float4*)&g_QKV[(b*256+q)*768 + tid*4];
    else if (tid < 128) *(float4*)&sBsh[(tid-64)*4]  = *(const float4*)&b_ss[(tid-64)*4];
    else if (tid < 192) *(float4*)&sBsc[(tid-128)*4] = *(const float4*)&b_ss[256+(tid-128)*4];
    else if (tid < 208) *(float4*)&sBed[(tid-192)*4] = *(const float4*)&b_edges[(tid-192)*4];

    {
        float4 v0 = *(const float4*)(ep + (size_t)er0 * 64 + ec0);
        float4 v1 = *(const float4*)(ep + (size_t)er1 * 64 + ec1);
        *(float4*)&sE0[er0*68 + ec0] = v0;
        *(float4*)&sE0[er1*68 + ec1] = v1;
    }
    __syncthreads();

    for (int kt = 0; kt < 8; kt++) {
        float* sEc = (kt & 1) ? sE1 : sE0;
        float* sEn = (kt & 1) ? sE0 : sE1;

        int ktn = (kt + 1) & 7;
        float4 pf0 = *(const float4*)(ep + (size_t)(ktn*32 + er0) * 64 + ec0);
        float4 pf1 = *(const float4*)(ep + (size_t)(ktn*32 + er1) * 64 + ec1);

        // ---- GEMM1: shift(acc 0..7) + scale(acc 8..15), fp16 2-pass ----
        float acc[16][4];
#pragma unroll
        for (int i = 0; i < 16; i++) { acc[i][0]=acc[i][1]=acc[i][2]=acc[i][3]=0.f; }
#pragma unroll
        for (int ks = 0; ks < 4; ks++) {
            uint32_t Ah[4], Al[4];
            {
                int e0 = ks * 16 + 2 * t;
                float2 v00 = *(float2*)&sEc[r0*68 + e0];
                float2 v10 = *(float2*)&sEc[r1*68 + e0];
                float2 v01 = *(float2*)&sEc[r0*68 + e0 + 8];
                float2 v11 = *(float2*)&sEc[r1*68 + e0 + 8];
                split2h(v00.x, v00.y, Ah[0], Al[0]);
                split2h(v10.x, v10.y, Ah[1], Al[1]);
                split2h(v01.x, v01.y, Ah[2], Al[2]);
                split2h(v11.x, v11.y, Ah[3], Al[3]);
            }
#pragma unroll
            for (int tpi = 0; tpi < 4; tpi++) {
                uint4 bh = g_Wss[(ks*32 + 4*wn + tpi)*32 + lane];        // shift
                mma16816h(acc[2*tpi],   Ah, bh.x, bh.y);
                mma16816h(acc[2*tpi+1], Ah, bh.z, bh.w);
                mma16816h(acc[2*tpi],   Al, bh.x, bh.y);
                mma16816h(acc[2*tpi+1], Al, bh.z, bh.w);
                uint4 ch = g_Wss[(ks*32 + 16 + 4*wn + tpi)*32 + lane];   // scale
                mma16816h(acc[8+2*tpi],   Ah, ch.x, ch.y);
                mma16816h(acc[8+2*tpi+1], Ah, ch.z, ch.w);
                mma16816h(acc[8+2*tpi],   Al, ch.x, ch.y);
                mma16816h(acc[8+2*tpi+1], Al, ch.z, ch.w);
            }
        }

        *(float4*)&sEn[er0*68 + ec0] = pf0;
        *(float4*)&sEn[er1*68 + ec1] = pf1;

        // ---- epilogue: ne, logits, lrelu -> sA2 (fp16 hi/lo) ----
        const float* kr0 = &g_QKV[(b*256 + kt*32 + r0)*768 + 256];
        const float* kr1 = &g_QKV[(b*256 + kt*32 + r1)*768 + 256];
        float lg00 = 0.f, lg01 = 0.f, lg10 = 0.f, lg11 = 0.f;
#pragma unroll
        for (int lt = 0; lt < 8; lt++) {
            int c0 = wn * 64 + lt * 8 + 2 * t;
            float2 k0v = *(const float2*)(kr0 + c0);
            float2 k1v = *(const float2*)(kr1 + c0);
            float q0 = sQ[c0], q1 = sQ[c0+1];
            float qk00 = q0 * k0v.x, qk01 = q1 * k0v.y;
            float qk10 = q0 * k1v.x, qk11 = q1 * k1v.y;
            float ne00 = fmaf(qk00, acc[8+lt][0] + sBsc[c0],   qk00) + acc[lt][0] + sBsh[c0];
            float ne01 = fmaf(qk01, acc[8+lt][1] + sBsc[c0+1], qk01) + acc[lt][1] + sBsh[c0+1];
            float ne10 = fmaf(qk10, acc[8+lt][2] + sBsc[c0],   qk10) + acc[lt][2] + sBsh[c0];
            float ne11 = fmaf(qk11, acc[8+lt][3] + sBsc[c0+1], qk11) + acc[lt][3] + sBsh[c0+1];
            if (lt < 4) { lg00 += ne00 + ne01; lg10 += ne10 + ne11; }
            else        { lg01 += ne00 + ne01; lg11 += ne10 + ne11; }
            float p00 = ne00 > 0.f ? ne00 : 0.1f*ne00;
            float p01 = ne01 > 0.f ? ne01 : 0.1f*ne01;
            float p10 = ne10 > 0.f ? ne10 : 0.1f*ne10;
            float p11 = ne11 > 0.f ? ne11 : 0.1f*ne11;
            uint32_t h, l;
            int cp = wn * 32 + lt * 4 + t;
            split2h(p00, p01, h, l); sA2h[r0*132 + cp] = h; sA2l[r0*132 + cp] = l;
            split2h(p10, p11, h, l); sA2h[r1*132 + cp] = h; sA2l[r1*132 + cp] = l;
        }
        lg00 += __shfl_xor_sync(0xffffffffu, lg00, 1); lg00 += __shfl_xor_sync(0xffffffffu, lg00, 2);
        lg01 += __shfl_xor_sync(0xffffffffu, lg01, 1); lg01 += __shfl_xor_sync(0xffffffffu, lg01, 2);
        lg10 += __shfl_xor_sync(0xffffffffu, lg10, 1); lg10 += __shfl_xor_sync(0xffffffffu, lg10, 2);
        lg11 += __shfl_xor_sync(0xffffffffu, lg11, 1); lg11 += __shfl_xor_sync(0xffffffffu, lg11, 2);
        if (t == 0) {
            const float SC = 0.17677669529663687f;
            int kk = kt * 32;
            g_att[(((size_t)(b*8 + 2*wn+0))*256 + kk + r0)*256 + q] = lg00 * SC;
            g_att[(((size_t)(b*8 + 2*wn+1))*256 + kk + r0)*256 + q] = lg01 * SC;
            g_att[(((size_t)(b*8 + 2*wn+0))*256 + kk + r1)*256 + q] = lg10 * SC;
            g_att[(((size_t)(b*8 + 2*wn+1))*256 + kk + r1)*256 + q] = lg11 * SC;
        }
        __syncthreads();

        // ---- GEMM2: out = lrelu(ne)[32,256] @ W_edges[256,64], fp16 2-pass ----
        float c2a[4] = {}, c2b[4] = {};
#pragma unroll
        for (int ks = 0; ks < 16; ks++) {
            uint32_t ah[4], al[4];
            ah[0] = sA2h[r0*132 + ks*8 + t];     al[0] = sA2l[r0*132 + ks*8 + t];
            ah[1] = sA2h[r1*132 + ks*8 + t];     al[1] = sA2l[r1*132 + ks*8 + t];
            ah[2] = sA2h[r0*132 + ks*8 + 4 + t]; al[2] = sA2l[r0*132 + ks*8 + 4 + t];
            ah[3] = sA2h[r1*132 + ks*8 + 4 + t]; al[3] = sA2l[r1*132 + ks*8 + 4 + t];
            uint4 bh = g_Wed[(ks*4 + wn)*32 + lane];
            mma16816h(c2a, ah, bh.x, bh.y); mma16816h(c2b, ah, bh.z, bh.w);
            mma16816h(c2a, al, bh.x, bh.y); mma16816h(c2b, al, bh.z, bh.w);
        }
        float* op = out_edges + (((size_t)(b*256+q))*256 + kt*32)*64;
        {
            int e0 = wn * 16 + 2 * t;
            *(float2*)&op[r0*64 + e0]     = make_float2(c2a[0] + sBed[e0],   c2a[1] + sBed[e0+1]);
            *(float2*)&op[r1*64 + e0]     = make_float2(c2a[2] + sBed[e0],   c2a[3] + sBed[e0+1]);
            *(float2*)&op[r0*64 + e0 + 8] = make_float2(c2b[0] + sBed[e0+8], c2b[1] + sBed[e0+9]);
            *(float2*)&op[r1*64 + e0 + 8] = make_float2(c2b[2] + sBed[e0+8], c2b[3] + sBed[e0+9]);
        }
        __syncthreads();
    }
}

// ===== softmax over q for each (b,h,k) =====
__global__ void __launch_bounds__(256) softmax_q_kernel(float* __restrict__ lg)
{
    const int row = blockIdx.x * 8 + (threadIdx.x >> 5);
    const int lane = threadIdx.x & 31;
    float* p = lg + (size_t)row * 256;
    float4 v0 = *(float4*)&p[lane * 8];
    float4 v1 = *(float4*)&p[lane * 8 + 4];
    float v[8] = { v0.x, v0.y, v0.z, v0.w, v1.x, v1.y, v1.z, v1.w };
    float m = v[0];
#pragma unroll
    for (int i = 1; i < 8; i++) m = fmaxf(m, v[i]);
#pragma unroll
    for (int o = 16; o > 0; o >>= 1) m = fmaxf(m, __shfl_xor_sync(0xffffffffu, m, o));
    float s = 0.f;
#pragma unroll
    for (int i = 0; i < 8; i++) { v[i] = __expf(v[i] - m); s += v[i]; }
#pragma unroll
    for (int o = 16; o > 0; o >>= 1) s += __shfl_xor_sync(0xffffffffu, s, o);
    float inv = 1.f / s;
    *(float4*)&p[lane * 8]     = make_float4(v[0]*inv, v[1]*inv, v[2]*inv, v[3]*inv);
    *(float4*)&p[lane * 8 + 4] = make_float4(v[4]*inv, v[5]*inv, v[6]*inv, v[7]*inv);
}

// ===== attn @ V, k-split, atomics into zeroed g_wt =====
__global__ void __launch_bounds__(256) attnv2_kernel(const float* __restrict__ att)
{
    __shared__ float sv[32][32];
    const int b = blockIdx.z >> 3, h = blockIdx.z & 7;
    const int kc = blockIdx.y, qc = blockIdx.x;
    const int dg = threadIdx.x >> 6, qq = threadIdx.x & 63;
    const int q = qc * 64 + qq;
    {
        int row = threadIdx.x >> 3, c4 = (threadIdx.x & 7) << 2;
        *(float4*)&sv[row][c4] =
            *(const float4*)&g_QKV[((b << 8) + kc * 32 + row) * 768 + 512 + h * 32 + c4];
    }
    __syncthreads();
    const float* ap = att + (((size_t)((b << 3) + h)) * 256 + kc * 32) * 256 + q;
    float acc[8] = {};
#pragma unroll
    for (int kk = 0; kk < 32; kk++) {
        float a = ap[(size_t)kk * 256];
        float4 u0 = *(float4*)&sv[kk][dg * 8];
        float4 u1 = *(float4*)&sv[kk][dg * 8 + 4];
        acc[0]+=a*u0.x; acc[1]+=a*u0.y; acc[2]+=a*u0.z; acc[3]+=a*u0.w;
        acc[4]+=a*u1.x; acc[5]+=a*u1.y; acc[6]+=a*u1.z; acc[7]+=a*u1.w;
    }
    float* wp = &g_wt[((b << 8) + q) * 256 + h * 32 + dg * 8];
#pragma unroll
    for (int j = 0; j < 8; j++) atomicAdd(wp + j, acc[j]);
}

// ===== launch =====
extern "C" void kernel_launch(void* const* d_in, const int* in_sizes, int n_in,
                              void* d_out, int out_size)
{
    const float* nodes   = (const float*)d_in[0];
    const float* edges   = (const float*)d_in[1];
    const float* W_qkv   = (const float*)d_in[2];
    const float* b_qkv   = (const float*)d_in[3];
    const float* W_ss    = (const float*)d_in[4];
    const float* b_ss    = (const float*)d_in[5];
    const float* W_nodes = (const float*)d_in[6];
    const float* b_nodes = (const float*)d_in[7];
    const float* W_edges = (const float*)d_in[8];
    const float* b_edges = (const float*)d_in[9];

    float* out_nodes = (float*)d_out;
    float* out_edges = out_nodes + 512 * 256;

    float *qkvp = nullptr, *attp = nullptr, *wtp = nullptr;
    cudaGetSymbolAddress((void**)&qkvp, g_QKV);
    cudaGetSymbolAddress((void**)&attp, g_att);
    cudaGetSymbolAddress((void**)&wtp, g_wt);

    const int EDGE_SMEM = (4352 + 832 + 8448) * sizeof(float);   // 54528 B
    cudaFuncSetAttribute(edge_mma_kernel,
                         cudaFuncAttributeMaxDynamicSharedMemorySize, EDGE_SMEM);

    zero_wt_kernel<<<128, 256>>>();
    prep_wss_kernel<<<16, 256>>>(W_ss);
    prep_wed_kernel<<<8, 256>>>(W_edges);
    gemm_bias_kernel<<<(512/32)*(768/64), 256>>>(nodes, W_qkv, b_qkv, qkvp, 512, 256, 768);
    edge_mma_kernel<<<512, 256, EDGE_SMEM>>>(edges, b_ss, b_edges, out_edges);
    softmax_q_kernel<<<512, 256>>>(attp);
    attnv2_kernel<<<dim3(4, 8, 16), 256>>>(attp);
    gemm_bias_kernel<<<(512/32)*(256/64), 256>>>(wtp, W_nodes, b_nodes, out_nodes, 512, 256, 256);
}

// round 10
// speedup vs baseline: 3.4861x; 1.1067x over previous
#include <cuda_runtime.h>
#include <cuda_fp16.h>
#include <cstdint>

// ---------------------------------------------------------------------------
// mma.sync fp16 1-pass implementation. B=2,N=256,NODE=256,EDGE=64,H=8,D=32.
// Both operands rounded to fp16 (error model: 4 incoherent 2^-11 sources
// ~ 3.8e-4 rel; validated on bf16-1p/bf16-3p/fp16-2p datapoints).
// HMMA count 6.29M -> 3.15M.
// ---------------------------------------------------------------------------

__device__ __forceinline__ void mma16816h(float c[4], const uint32_t a[4],
                                          uint32_t b0, uint32_t b1) {
    asm volatile("mma.sync.aligned.m16n8k16.row.col.f32.f16.f16.f32 "
        "{%0,%1,%2,%3},{%4,%5,%6,%7},{%8,%9},{%0,%1,%2,%3};"
        : "+f"(c[0]), "+f"(c[1]), "+f"(c[2]), "+f"(c[3])
        : "r"(a[0]), "r"(a[1]), "r"(a[2]), "r"(a[3]), "r"(b0), "r"(b1));
}
__device__ __forceinline__ uint32_t pack2h(float v0, float v1) {
    __half2 hh = __floats2half2_rn(v0, v1);
    return *(uint32_t*)&hh;
}

// ===== scratch =====
__device__ float g_QKV[512 * 768];          // [b*256+n][768] q|k|v
__device__ float g_att[2 * 8 * 256 * 256];  // [b][h][k][q]
__device__ float g_wt[512 * 256];
__device__ uint4 g_Wss[4096];   // [ks4][tp32][lane32] frag-linear fp16x2
__device__ uint4 g_Wed[2048];   // [ks16][tp4][lane32]

__global__ void __launch_bounds__(256) zero_wt_kernel()
{
    int i = blockIdx.x * 256 + threadIdx.x;
    ((float4*)g_wt)[i] = make_float4(0.f, 0.f, 0.f, 0.f);
}

// ===== prep: W_ss frag image (fp16) =====
__global__ void __launch_bounds__(256) prep_wss_kernel(const float* __restrict__ W_ss)
{
    int idx = blockIdx.x * 256 + threadIdx.x;    // 4096 uint4
    int lane = idx & 31, tp = (idx >> 5) & 31, ks = idx >> 10;
    int gq = lane >> 2, tq = lane & 3;
    uint32_t r4[4];
#pragma unroll
    for (int r = 0; r < 4; r++) {
        int tile = 2 * tp + (r >> 1);
        int bsel = r & 1;
        int n = tile * 8 + gq;
        int e0 = ks * 16 + 2 * tq + 8 * bsel;
        r4[r] = pack2h(W_ss[e0 * 512 + n], W_ss[(e0 + 1) * 512 + n]);
    }
    g_Wss[idx] = make_uint4(r4[0], r4[1], r4[2], r4[3]);
}
// ===== prep: W_edges frag image (fp16) =====
__global__ void __launch_bounds__(256) prep_wed_kernel(const float* __restrict__ W_edges)
{
    int idx = blockIdx.x * 256 + threadIdx.x;    // 2048 uint4
    int lane = idx & 31, tp = (idx >> 5) & 3, ks = idx >> 7;
    int gq = lane >> 2, tq = lane & 3;
    uint32_t r4[4];
#pragma unroll
    for (int r = 0; r < 4; r++) {
        int tile = 2 * tp + (r >> 1);
        int bsel = r & 1;
        int e = tile * 8 + gq;
        int c0 = ks * 16 + 2 * tq + 8 * bsel;
        r4[r] = pack2h(W_edges[c0 * 64 + e], W_edges[(c0 + 1) * 64 + e]);
    }
    g_Wed[idx] = make_uint4(r4[0], r4[1], r4[2], r4[3]);
}

// ===== small GEMM with bias, 32x64 tiles, double-buffered k-loop =====
__global__ void __launch_bounds__(256) gemm_bias_kernel(
    const float* __restrict__ A, const float* __restrict__ B,
    const float* __restrict__ bias, float* __restrict__ C, int M, int K, int N)
{
    __shared__ float sA[2][16][33];
    __shared__ float sB[2][16][64];
    const int nb = N >> 6;
    const int m0 = (blockIdx.x / nb) << 5, n0 = (blockIdx.x % nb) << 6;
    const int tm = threadIdx.x >> 4, tn = threadIdx.x & 15;
    const int tt = threadIdx.x;
    const int am = tt >> 2, ak4 = (tt & 3) << 2;
    const int bk = tt >> 4, bn4 = (tt & 15) << 2;
    const int nk = K >> 4;

    float4 aR, bR;
    if (tt < 128) aR = *(const float4*)&A[(m0 + am) * K + ak4];
    bR = *(const float4*)&B[bk * N + n0 + bn4];
    if (tt < 128) {
        sA[0][ak4+0][am] = aR.x; sA[0][ak4+1][am] = aR.y;
        sA[0][ak4+2][am] = aR.z; sA[0][ak4+3][am] = aR.w;
    }
    *(float4*)&sB[0][bk][bn4] = bR;
    __syncthreads();

    float acc[2][4] = {};
    for (int kc = 0; kc < nk; kc++) {
        const int cur = kc & 1;
        if (kc + 1 < nk) {
            if (tt < 128) aR = *(const float4*)&A[(m0 + am) * K + (kc+1)*16 + ak4];
            bR = *(const float4*)&B[((kc+1)*16 + bk) * N + n0 + bn4];
        }
#pragma unroll
        for (int k2 = 0; k2 < 16; k2++) {
            float a0 = sA[cur][k2][tm*2+0], a1 = sA[cur][k2][tm*2+1];
            float4 b4 = *(float4*)&sB[cur][k2][tn*4];
            acc[0][0]+=a0*b4.x; acc[0][1]+=a0*b4.y; acc[0][2]+=a0*b4.z; acc[0][3]+=a0*b4.w;
            acc[1][0]+=a1*b4.x; acc[1][1]+=a1*b4.y; acc[1][2]+=a1*b4.z; acc[1][3]+=a1*b4.w;
        }
        if (kc + 1 < nk) {
            const int nxt = cur ^ 1;
            if (tt < 128) {
                sA[nxt][ak4+0][am] = aR.x; sA[nxt][ak4+1][am] = aR.y;
                sA[nxt][ak4+2][am] = aR.z; sA[nxt][ak4+3][am] = aR.w;
            }
            *(float4*)&sB[nxt][bk][bn4] = bR;
        }
        __syncthreads();
    }
    float4 bb = *(const float4*)&bias[n0 + tn * 4];
#pragma unroll
    for (int i = 0; i < 2; i++)
        *(float4*)&C[(m0 + tm*2 + i) * N + n0 + tn*4] =
            make_float4(acc[i][0]+bb.x, acc[i][1]+bb.y, acc[i][2]+bb.z, acc[i][3]+bb.w);
}

// ===== main edge kernel: mma.sync fp16 1-pass, CTA=(b,q), 8 warps 2Mx4N =====
__global__ void __launch_bounds__(256, 2) edge_mma_kernel(
    const float* __restrict__ edges, const float* __restrict__ b_ss,
    const float* __restrict__ b_edges, float* __restrict__ out_edges)
{
    extern __shared__ float sm[];
    float* sE0  = sm;                    // [32][68] buffer 0
    float* sE1  = sm + 2176;             // [32][68] buffer 1
    float* sQ   = sm + 4352;             // 256
    float* sBsh = sQ + 256;              // 256
    float* sBsc = sBsh + 256;            // 256
    float* sBed = sBsc + 256;            // 64
    uint32_t* sA2h = (uint32_t*)(sBed + 64);  // [32][132] fp16x2

    const int tid = threadIdx.x;
    const int warp = tid >> 5, lane = tid & 31;
    const int wm = warp >> 2, wn = warp & 3;
    const int g = lane >> 2, t = lane & 3;
    const int b = blockIdx.x >> 8, q = blockIdx.x & 255;
    const int r0 = wm * 16 + g, r1 = r0 + 8;

    const int er0 = tid >> 4,         ec0 = (tid & 15) << 2;
    const int er1 = (tid + 256) >> 4, ec1 = ec0;
    const float* ep = edges + (((size_t)(b * 256 + q)) * 256) * 64;

    if (tid < 64)       *(float4*)&sQ[tid*4]   = *(const float4*)&g_QKV[(b*256+q)*768 + tid*4];
    else if (tid < 128) *(float4*)&sBsh[(tid-64)*4]  = *(const float4*)&b_ss[(tid-64)*4];
    else if (tid < 192) *(float4*)&sBsc[(tid-128)*4] = *(const float4*)&b_ss[256+(tid-128)*4];
    else if (tid < 208) *(float4*)&sBed[(tid-192)*4] = *(const float4*)&b_edges[(tid-192)*4];

    {
        float4 v0 = *(const float4*)(ep + (size_t)er0 * 64 + ec0);
        float4 v1 = *(const float4*)(ep + (size_t)er1 * 64 + ec1);
        *(float4*)&sE0[er0*68 + ec0] = v0;
        *(float4*)&sE0[er1*68 + ec1] = v1;
    }
    __syncthreads();

    for (int kt = 0; kt < 8; kt++) {
        float* sEc = (kt & 1) ? sE1 : sE0;
        float* sEn = (kt & 1) ? sE0 : sE1;

        int ktn = (kt + 1) & 7;
        float4 pf0 = *(const float4*)(ep + (size_t)(ktn*32 + er0) * 64 + ec0);
        float4 pf1 = *(const float4*)(ep + (size_t)(ktn*32 + er1) * 64 + ec1);

        // ---- GEMM1: shift(acc 0..7) + scale(acc 8..15), fp16 1-pass ----
        float acc[16][4];
#pragma unroll
        for (int i = 0; i < 16; i++) { acc[i][0]=acc[i][1]=acc[i][2]=acc[i][3]=0.f; }
#pragma unroll
        for (int ks = 0; ks < 4; ks++) {
            uint32_t Ah[4];
            {
                int e0 = ks * 16 + 2 * t;
                float2 v00 = *(float2*)&sEc[r0*68 + e0];
                float2 v10 = *(float2*)&sEc[r1*68 + e0];
                float2 v01 = *(float2*)&sEc[r0*68 + e0 + 8];
                float2 v11 = *(float2*)&sEc[r1*68 + e0 + 8];
                Ah[0] = pack2h(v00.x, v00.y);
                Ah[1] = pack2h(v10.x, v10.y);
                Ah[2] = pack2h(v01.x, v01.y);
                Ah[3] = pack2h(v11.x, v11.y);
            }
#pragma unroll
            for (int tpi = 0; tpi < 4; tpi++) {
                uint4 bh = g_Wss[(ks*32 + 4*wn + tpi)*32 + lane];        // shift
                mma16816h(acc[2*tpi],   Ah, bh.x, bh.y);
                mma16816h(acc[2*tpi+1], Ah, bh.z, bh.w);
                uint4 ch = g_Wss[(ks*32 + 16 + 4*wn + tpi)*32 + lane];   // scale
                mma16816h(acc[8+2*tpi],   Ah, ch.x, ch.y);
                mma16816h(acc[8+2*tpi+1], Ah, ch.z, ch.w);
            }
        }

        *(float4*)&sEn[er0*68 + ec0] = pf0;
        *(float4*)&sEn[er1*68 + ec1] = pf1;

        // ---- epilogue: ne, logits, lrelu -> sA2 (fp16) ----
        const float* kr0 = &g_QKV[(b*256 + kt*32 + r0)*768 + 256];
        const float* kr1 = &g_QKV[(b*256 + kt*32 + r1)*768 + 256];
        float lg00 = 0.f, lg01 = 0.f, lg10 = 0.f, lg11 = 0.f;
#pragma unroll
        for (int lt = 0; lt < 8; lt++) {
            int c0 = wn * 64 + lt * 8 + 2 * t;
            float2 k0v = *(const float2*)(kr0 + c0);
            float2 k1v = *(const float2*)(kr1 + c0);
            float q0 = sQ[c0], q1 = sQ[c0+1];
            float qk00 = q0 * k0v.x, qk01 = q1 * k0v.y;
            float qk10 = q0 * k1v.x, qk11 = q1 * k1v.y;
            float ne00 = fmaf(qk00, acc[8+lt][0] + sBsc[c0],   qk00) + acc[lt][0] + sBsh[c0];
            float ne01 = fmaf(qk01, acc[8+lt][1] + sBsc[c0+1], qk01) + acc[lt][1] + sBsh[c0+1];
            float ne10 = fmaf(qk10, acc[8+lt][2] + sBsc[c0],   qk10) + acc[lt][2] + sBsh[c0];
            float ne11 = fmaf(qk11, acc[8+lt][3] + sBsc[c0+1], qk11) + acc[lt][3] + sBsh[c0+1];
            if (lt < 4) { lg00 += ne00 + ne01; lg10 += ne10 + ne11; }
            else        { lg01 += ne00 + ne01; lg11 += ne10 + ne11; }
            float p00 = ne00 > 0.f ? ne00 : 0.1f*ne00;
            float p01 = ne01 > 0.f ? ne01 : 0.1f*ne01;
            float p10 = ne10 > 0.f ? ne10 : 0.1f*ne10;
            float p11 = ne11 > 0.f ? ne11 : 0.1f*ne11;
            int cp = wn * 32 + lt * 4 + t;
            sA2h[r0*132 + cp] = pack2h(p00, p01);
            sA2h[r1*132 + cp] = pack2h(p10, p11);
        }
        lg00 += __shfl_xor_sync(0xffffffffu, lg00, 1); lg00 += __shfl_xor_sync(0xffffffffu, lg00, 2);
        lg01 += __shfl_xor_sync(0xffffffffu, lg01, 1); lg01 += __shfl_xor_sync(0xffffffffu, lg01, 2);
        lg10 += __shfl_xor_sync(0xffffffffu, lg10, 1); lg10 += __shfl_xor_sync(0xffffffffu, lg10, 2);
        lg11 += __shfl_xor_sync(0xffffffffu, lg11, 1); lg11 += __shfl_xor_sync(0xffffffffu, lg11, 2);
        if (t == 0) {
            const float SC = 0.17677669529663687f;
            int kk = kt * 32;
            g_att[(((size_t)(b*8 + 2*wn+0))*256 + kk + r0)*256 + q] = lg00 * SC;
            g_att[(((size_t)(b*8 + 2*wn+1))*256 + kk + r0)*256 + q] = lg01 * SC;
            g_att[(((size_t)(b*8 + 2*wn+0))*256 + kk + r1)*256 + q] = lg10 * SC;
            g_att[(((size_t)(b*8 + 2*wn+1))*256 + kk + r1)*256 + q] = lg11 * SC;
        }
        __syncthreads();

        // ---- GEMM2: out = lrelu(ne)[32,256] @ W_edges[256,64], fp16 1-pass ----
        float c2a[4] = {}, c2b[4] = {};
#pragma unroll
        for (int ks = 0; ks < 16; ks++) {
            uint32_t ah[4];
            ah[0] = sA2h[r0*132 + ks*8 + t];
            ah[1] = sA2h[r1*132 + ks*8 + t];
            ah[2] = sA2h[r0*132 + ks*8 + 4 + t];
            ah[3] = sA2h[r1*132 + ks*8 + 4 + t];
            uint4 bh = g_Wed[(ks*4 + wn)*32 + lane];
            mma16816h(c2a, ah, bh.x, bh.y); mma16816h(c2b, ah, bh.z, bh.w);
        }
        float* op = out_edges + (((size_t)(b*256+q))*256 + kt*32)*64;
        {
            int e0 = wn * 16 + 2 * t;
            *(float2*)&op[r0*64 + e0]     = make_float2(c2a[0] + sBed[e0],   c2a[1] + sBed[e0+1]);
            *(float2*)&op[r1*64 + e0]     = make_float2(c2a[2] + sBed[e0],   c2a[3] + sBed[e0+1]);
            *(float2*)&op[r0*64 + e0 + 8] = make_float2(c2b[0] + sBed[e0+8], c2b[1] + sBed[e0+9]);
            *(float2*)&op[r1*64 + e0 + 8] = make_float2(c2b[2] + sBed[e0+8], c2b[3] + sBed[e0+9]);
        }
        __syncthreads();
    }
}

// ===== softmax over q for each (b,h,k) =====
__global__ void __launch_bounds__(256) softmax_q_kernel(float* __restrict__ lg)
{
    const int row = blockIdx.x * 8 + (threadIdx.x >> 5);
    const int lane = threadIdx.x & 31;
    float* p = lg + (size_t)row * 256;
    float4 v0 = *(float4*)&p[lane * 8];
    float4 v1 = *(float4*)&p[lane * 8 + 4];
    float v[8] = { v0.x, v0.y, v0.z, v0.w, v1.x, v1.y, v1.z, v1.w };
    float m = v[0];
#pragma unroll
    for (int i = 1; i < 8; i++) m = fmaxf(m, v[i]);
#pragma unroll
    for (int o = 16; o > 0; o >>= 1) m = fmaxf(m, __shfl_xor_sync(0xffffffffu, m, o));
    float s = 0.f;
#pragma unroll
    for (int i = 0; i < 8; i++) { v[i] = __expf(v[i] - m); s += v[i]; }
#pragma unroll
    for (int o = 16; o > 0; o >>= 1) s += __shfl_xor_sync(0xffffffffu, s, o);
    float inv = 1.f / s;
    *(float4*)&p[lane * 8]     = make_float4(v[0]*inv, v[1]*inv, v[2]*inv, v[3]*inv);
    *(float4*)&p[lane * 8 + 4] = make_float4(v[4]*inv, v[5]*inv, v[6]*inv, v[7]*inv);
}

// ===== attn @ V, k-split, atomics into zeroed g_wt =====
__global__ void __launch_bounds__(256) attnv2_kernel(const float* __restrict__ att)
{
    __shared__ float sv[32][32];
    const int b = blockIdx.z >> 3, h = blockIdx.z & 7;
    const int kc = blockIdx.y, qc = blockIdx.x;
    const int dg = threadIdx.x >> 6, qq = threadIdx.x & 63;
    const int q = qc * 64 + qq;
    {
        int row = threadIdx.x >> 3, c4 = (threadIdx.x & 7) << 2;
        *(float4*)&sv[row][c4] =
            *(const float4*)&g_QKV[((b << 8) + kc * 32 + row) * 768 + 512 + h * 32 + c4];
    }
    __syncthreads();
    const float* ap = att + (((size_t)((b << 3) + h)) * 256 + kc * 32) * 256 + q;
    float acc[8] = {};
#pragma unroll
    for (int kk = 0; kk < 32; kk++) {
        float a = ap[(size_t)kk * 256];
        float4 u0 = *(float4*)&sv[kk][dg * 8];
        float4 u1 = *(float4*)&sv[kk][dg * 8 + 4];
        acc[0]+=a*u0.x; acc[1]+=a*u0.y; acc[2]+=a*u0.z; acc[3]+=a*u0.w;
        acc[4]+=a*u1.x; acc[5]+=a*u1.y; acc[6]+=a*u1.z; acc[7]+=a*u1.w;
    }
    float* wp = &g_wt[((b << 8) + q) * 256 + h * 32 + dg * 8];
#pragma unroll
    for (int j = 0; j < 8; j++) atomicAdd(wp + j, acc[j]);
}

// ===== launch =====
extern "C" void kernel_launch(void* const* d_in, const int* in_sizes, int n_in,
                              void* d_out, int out_size)
{
    const float* nodes   = (const float*)d_in[0];
    const float* edges   = (const float*)d_in[1];
    const float* W_qkv   = (const float*)d_in[2];
    const float* b_qkv   = (const float*)d_in[3];
    const float* W_ss    = (const float*)d_in[4];
    const float* b_ss    = (const float*)d_in[5];
    const float* W_nodes = (const float*)d_in[6];
    const float* b_nodes = (const float*)d_in[7];
    const float* W_edges = (const float*)d_in[8];
    const float* b_edges = (const float*)d_in[9];

    float* out_nodes = (float*)d_out;
    float* out_edges = out_nodes + 512 * 256;

    float *qkvp = nullptr, *attp = nullptr, *wtp = nullptr;
    cudaGetSymbolAddress((void**)&qkvp, g_QKV);
    cudaGetSymbolAddress((void**)&attp, g_att);
    cudaGetSymbolAddress((void**)&wtp, g_wt);

    const int EDGE_SMEM = (4352 + 832 + 4224) * sizeof(float);   // 37632 B
    cudaFuncSetAttribute(edge_mma_kernel,
                         cudaFuncAttributeMaxDynamicSharedMemorySize, EDGE_SMEM);

    zero_wt_kernel<<<128, 256>>>();
    prep_wss_kernel<<<16, 256>>>(W_ss);
    prep_wed_kernel<<<8, 256>>>(W_edges);
    gemm_bias_kernel<<<(512/32)*(768/64), 256>>>(nodes, W_qkv, b_qkv, qkvp, 512, 256, 768);
    edge_mma_kernel<<<512, 256, EDGE_SMEM>>>(edges, b_ss, b_edges, out_edges);
    softmax_q_kernel<<<512, 256>>>(attp);
    attnv2_kernel<<<dim3(4, 8, 16), 256>>>(attp);
    gemm_bias_kernel<<<(512/32)*(256/64), 256>>>(wtp, W_nodes, b_nodes, out_nodes, 512, 256, 256);
}